// round 5
// baseline (speedup 1.0000x reference)
#include <cuda_runtime.h>
#include <math.h>
#include <float.h>
#include <stdint.h>

#define B_      2
#define N_KP    256
#define C_      256
#define HF_     64
#define WF_     64
#define ROI_    15
#define P2_     225
#define HID_    256
#define HEADS_  8
#define DH_     32
#define DEPTH_  3
#define FFN_    1024
#define NQ_     16
#define BN_     512          // B_*N_KP
#define MROWS_  8192         // BN_*NQ_
#define MMEM_   115200       // BN_*P2_
#define SPAD_   240          // padded S row
#define LN_EPS_ 1e-5f

#define GEMM_SMEM_  (3 * 128 * 20 * 2 * 4)                 // 61440 B
#define ATTN_SMEM_  (128 * 244 * 4 + 3 * 16 * 136 * 4)     // 151040 B

// ---------------- scratch ----------------
__device__ float g_imgT[(size_t)B_ * HF_ * WF_ * C_];
__device__ float g_feat[(size_t)MMEM_ * C_];
__device__ float g_mem [(size_t)MMEM_ * C_];
__device__ float g_tgt [(size_t)MROWS_ * HID_];
__device__ float g_y   [(size_t)MROWS_ * HID_];
__device__ float g_qkv [(size_t)MROWS_ * 3 * HID_];
__device__ float g_ctx [(size_t)MROWS_ * HID_];
__device__ float g_qc  [(size_t)MROWS_ * HID_];
__device__ float g_u   [(size_t)BN_ * 128 * HID_];
__device__ float g_s   [(size_t)BN_ * 128 * SPAD_];
__device__ float g_ffn [(size_t)MROWS_ * FFN_];
__device__ unsigned char g_valid[BN_];

// ---------------- helpers ----------------
__device__ __forceinline__ void mma_tf32(float* c, const uint32_t* a, const uint32_t* b) {
    asm volatile(
        "mma.sync.aligned.m16n8k8.row.col.f32.tf32.tf32.f32 "
        "{%0,%1,%2,%3}, {%4,%5,%6,%7}, {%8,%9}, {%0,%1,%2,%3};\n"
        : "+f"(c[0]), "+f"(c[1]), "+f"(c[2]), "+f"(c[3])
        : "r"(a[0]), "r"(a[1]), "r"(a[2]), "r"(a[3]), "r"(b[0]), "r"(b[1]));
}

__device__ __forceinline__ void cpa16(void* smem_ptr, const void* gptr, bool pred) {
    uint32_t sa = (uint32_t)__cvta_generic_to_shared(smem_ptr);
    int sz = pred ? 16 : 0;
    asm volatile("cp.async.cg.shared.global [%0], [%1], 16, %2;\n"
                 :: "r"(sa), "l"(gptr), "r"(sz));
}
#define CPA_COMMIT() asm volatile("cp.async.commit_group;\n")
#define CPA_WAIT(n)  asm volatile("cp.async.wait_group %0;\n" :: "n"(n))

// ---------------- mask decode ----------------
__global__ void decode_mask(const unsigned char* __restrict__ m, unsigned char* __restrict__ out) {
    __shared__ int flag;
    if (threadIdx.x == 0) flag = 0;
    __syncthreads();
    int i = threadIdx.x;
    unsigned char v8 = m[i];
    if ((i & 3) != 0 && v8 != 0) atomicOr(&flag, 1);
    __syncthreads();
    if (flag) out[i] = (v8 != 0);
    else      out[i] = (((const int*)m)[i] != 0);
}

// ---------------- image transpose (B,C,H,W) -> (B,H,W,C) ----------------
__global__ void transpose_img(const float* __restrict__ img) {
    int x = blockIdx.x, y = blockIdx.y, b = blockIdx.z, c = threadIdx.x;
    g_imgT[(((size_t)b * HF_ + y) * WF_ + x) * C_ + c] =
        img[(((size_t)b * C_ + c) * HF_ + y) * WF_ + x];
}

// ---------------- ROI bilinear gather ----------------
__global__ __launch_bounds__(256) void roi_gather(const float* __restrict__ kp) {
    int p = blockIdx.x, n = blockIdx.y, b = blockIdx.z, c = threadIdx.x;
    int iy = p / ROI_, ix = p % ROI_;
    float rc0 = rintf(kp[((size_t)b * N_KP + n) * 2 + 0]);
    float rc1 = rintf(kp[((size_t)b * N_KP + n) * 2 + 1]);
    float gy = rc0 + (float)(iy - 7);
    float gx = rc1 + (float)(ix - 7);
    float gxn = __fdiv_rn(gx, 511.0f) * 2.0f - 1.0f;
    float gyn = __fdiv_rn(gy, 511.0f) * 2.0f - 1.0f;
    bool invalid = (gxn < -1.0f) || (gyn < -1.0f) || (gxn > 1.0f) || (gyn > 1.0f);
    float* dst = g_feat + ((size_t)((b * N_KP + n) * P2_ + p)) * C_;
    if (invalid) { dst[c] = 0.0f; return; }
    float x = ((gxn + 1.0f) * (float)WF_ - 1.0f) * 0.5f;
    float y = ((gyn + 1.0f) * (float)HF_ - 1.0f) * 0.5f;
    float x0f = floorf(x), y0f = floorf(y);
    float wx = x - x0f, wy = y - y0f;
    int x0 = (int)x0f, y0 = (int)y0f;
    int x1 = x0 + 1, y1 = y0 + 1;
    float w00 = (1.0f - wy) * (1.0f - wx);
    float w01 = (1.0f - wy) * wx;
    float w10 = wy * (1.0f - wx);
    float w11 = wy * wx;
    float acc = 0.0f;
    if (y0 >= 0 && y0 < HF_) {
        const float* rowp = g_imgT + ((size_t)(b * HF_ + y0) * WF_) * C_;
        if (x0 >= 0 && x0 < WF_) acc += w00 * rowp[(size_t)x0 * C_ + c];
        if (x1 >= 0 && x1 < WF_) acc += w01 * rowp[(size_t)x1 * C_ + c];
    }
    if (y1 >= 0 && y1 < HF_) {
        const float* rowp = g_imgT + ((size_t)(b * HF_ + y1) * WF_) * C_;
        if (x0 >= 0 && x0 < WF_) acc += w10 * rowp[(size_t)x0 * C_ + c];
        if (x1 >= 0 && x1 < WF_) acc += w11 * rowp[(size_t)x1 * C_ + c];
    }
    dst[c] = acc;
}

// ================= tf32 GEMM: C = alpha*A@B^T [+bias][+res][relu] =================
// B is (N,K) row-major. Block 128x128, K-tile 16, 3-stage cp.async, 1 barrier/tile.
// Raw fp32 fed to tf32 MMA (HW truncates low mantissa bits).
// Requires K multiple of 16, KT >= 2, A rows 16B-chunk readable.
#define AS_(st,m,k)  Asm[(((st) * 128 + (m)) * 20) + (k)]
#define BT_(st,n,k)  Bsm[(((st) * 128 + (n)) * 20) + (k)]
template<bool HAS_BIAS, bool HAS_RES, bool RELU>
__global__ __launch_bounds__(256, 2) void gemm_tc(
    const float* __restrict__ A, const float* __restrict__ B,
    const float* __restrict__ bias, const float* __restrict__ Res,
    float* __restrict__ C,
    int M, int N, int K, int lda, int ldb, int ldc,
    long long sA, long long sB, long long sC, float alpha)
{
    extern __shared__ float dsm[];
    float* Asm = dsm;
    float* Bsm = dsm + 3 * 128 * 20;

    long long z = blockIdx.z;
    A += z * sA; B += z * sB; C += z * sC;
    if (HAS_RES) Res += z * sC;

    int m0 = blockIdx.y * 128, n0 = blockIdx.x * 128;
    int t = threadIdx.x;
    int wid = t >> 5, lane = t & 31;
    int warp_m = wid >> 2;
    int warp_n = wid & 3;
    int g = lane >> 2, tq = lane & 3;

    int a_m0 = (t >> 2);
    int a_k  = (t & 3) * 4;

    float acc[4][4][4];
#pragma unroll
    for (int i = 0; i < 4; i++)
#pragma unroll
        for (int j = 0; j < 4; j++)
#pragma unroll
            for (int r = 0; r < 4; r++) acc[i][j][r] = 0.0f;

    int KT = K >> 4;

    auto load_tile = [&](int st, int k0) {
#pragma unroll
        for (int i = 0; i < 2; i++) {
            int m = a_m0 + i * 64;
            int gm = m0 + m, gk = k0 + a_k;
            cpa16(&AS_(st, m, a_k), A + (size_t)gm * lda + gk, gm < M);
        }
#pragma unroll
        for (int i = 0; i < 2; i++) {
            int n = a_m0 + i * 64;
            int gn = n0 + n, gk = k0 + a_k;
            cpa16(&BT_(st, n, a_k), B + (size_t)gn * ldb + gk, gn < N);
        }
    };

    load_tile(0, 0); CPA_COMMIT();
    load_tile(1, 16); CPA_COMMIT();

    for (int kt = 0; kt < KT; kt++) {
        if (kt + 1 < KT) { CPA_WAIT(1); } else { CPA_WAIT(0); }
        __syncthreads();
        int st = kt % 3;
#pragma unroll
        for (int ks = 0; ks < 16; ks += 8) {
            uint32_t af[4][4];
#pragma unroll
            for (int mt = 0; mt < 4; mt++) {
                int mrow = warp_m * 64 + mt * 16;
                af[mt][0] = __float_as_uint(AS_(st, mrow + g,     ks + tq));
                af[mt][1] = __float_as_uint(AS_(st, mrow + g + 8, ks + tq));
                af[mt][2] = __float_as_uint(AS_(st, mrow + g,     ks + tq + 4));
                af[mt][3] = __float_as_uint(AS_(st, mrow + g + 8, ks + tq + 4));
            }
            uint32_t bf[4][2];
#pragma unroll
            for (int nt = 0; nt < 4; nt++) {
                int ncol = warp_n * 32 + nt * 8 + g;
                bf[nt][0] = __float_as_uint(BT_(st, ncol, ks + tq));
                bf[nt][1] = __float_as_uint(BT_(st, ncol, ks + tq + 4));
            }
#pragma unroll
            for (int mt = 0; mt < 4; mt++)
#pragma unroll
                for (int nt = 0; nt < 4; nt++)
                    mma_tf32(acc[mt][nt], af[mt], bf[nt]);
        }
        if (kt + 2 < KT) { load_tile((kt + 2) % 3, (kt + 2) * 16); CPA_COMMIT(); }
    }

    // ---- epilogue ----
#pragma unroll
    for (int mt = 0; mt < 4; mt++) {
        int row0 = m0 + warp_m * 64 + mt * 16 + g;
#pragma unroll
        for (int nt = 0; nt < 4; nt++) {
            int col = n0 + warp_n * 32 + nt * 8 + tq * 2;
#pragma unroll
            for (int half = 0; half < 2; half++) {
                int row = row0 + half * 8;
                if (row >= M) continue;
                float v0 = acc[mt][nt][half * 2 + 0] * alpha;
                float v1 = acc[mt][nt][half * 2 + 1] * alpha;
                if (col < N) {
                    float v = v0;
                    if (HAS_BIAS) v += bias[col];
                    if (HAS_RES)  v += Res[(size_t)row * ldc + col];
                    if (RELU)     v = fmaxf(v, 0.0f);
                    C[(size_t)row * ldc + col] = v;
                }
                if (col + 1 < N) {
                    float v = v1;
                    if (HAS_BIAS) v += bias[col + 1];
                    if (HAS_RES)  v += Res[(size_t)row * ldc + col + 1];
                    if (RELU)     v = fmaxf(v, 0.0f);
                    C[(size_t)row * ldc + col + 1] = v;
                }
            }
        }
    }
}

// ================= fused softmax + T = A @ mem (per bn) =================
// grid (2, BN_): blockIdx.x = c-half, blockIdx.y = bn. 256 threads.
// Loads raw S[128x240] to smem, softmax in place (mask/valid/k0), then
// MMA loop over K=240 keys with A resident, B (mem) 3-stage cp.async.
__global__ __launch_bounds__(256) void attn_t() {
    extern __shared__ float dsm[];
    float* Sa  = dsm;                  // [128][244]
    float* Bsm = dsm + 128 * 244;      // [3][16][136]
#define SA_(r,k)     Sa[(r) * 244 + (k)]
#define BS_(st,k,n)  Bsm[(((st) * 16 + (k)) * 136) + (n)]

    int bn = blockIdx.y;
    int n0 = blockIdx.x * 128;
    int t = threadIdx.x;
    int wid = t >> 5, lane = t & 31;
    int warp_m = wid >> 2, warp_n = wid & 3;
    int g = lane >> 2, tq = lane & 3;

    // ---- load S tile (128 x 240) ----
    const float* Sg = g_s + (size_t)bn * 128 * SPAD_;
#pragma unroll
    for (int j = 0; j < 30; j++) {
        int i = t + j * 256;
        int row = i / 60, c4 = (i % 60) * 4;
        cpa16(&SA_(row, c4), Sg + (size_t)row * SPAD_ + c4, true);
    }
    CPA_COMMIT(); CPA_WAIT(0);
    __syncthreads();

    // ---- softmax in smem: warp wid handles rows wid*16 .. +15 ----
    bool v = g_valid[bn] != 0;
    for (int rr = 0; rr < 16; rr++) {
        int r = wid * 16 + rr;
        float vals[8];
        float m = -FLT_MAX;
#pragma unroll
        for (int i = 0; i < 8; i++) {
            int k = lane + i * 32;
            bool active = (k < P2_) && (v || k == 0);
            float x = active ? SA_(r, k) : 0.0f;
            vals[i] = active ? x : -INFINITY;
            m = fmaxf(m, vals[i]);
        }
#pragma unroll
        for (int o = 16; o; o >>= 1) m = fmaxf(m, __shfl_xor_sync(0xffffffffu, m, o));
        float sum = 0.0f;
#pragma unroll
        for (int i = 0; i < 8; i++) {
            int k = lane + i * 32;
            bool active = (k < P2_) && (v || k == 0);
            float e = active ? expf(vals[i] - m) : 0.0f;
            vals[i] = e;
            sum += e;
        }
#pragma unroll
        for (int o = 16; o; o >>= 1) sum += __shfl_xor_sync(0xffffffffu, sum, o);
        float inv = 1.0f / sum;
#pragma unroll
        for (int i = 0; i < 8; i++) {
            int k = lane + i * 32;
            if (k < P2_)        SA_(r, k) = vals[i] * inv;
            else if (k < SPAD_) SA_(r, k) = 0.0f;
        }
    }
    __syncthreads();

    // ---- T = A @ mem : M=128, N=128 (this half), K=240 ----
    const float* Bg = g_mem + (size_t)bn * P2_ * HID_;
    int nt_k = t >> 4;
    int nt_n = (t & 15) * 8;

    float acc[4][4][4];
#pragma unroll
    for (int i = 0; i < 4; i++)
#pragma unroll
        for (int j = 0; j < 4; j++)
#pragma unroll
            for (int r = 0; r < 4; r++) acc[i][j][r] = 0.0f;

    const int KT = SPAD_ / 16;   // 15

    auto loadB = [&](int st, int k0) {
        int gk = k0 + nt_k;
        const float* src = Bg + (size_t)gk * HID_ + n0 + nt_n;
        cpa16(&BS_(st, nt_k, nt_n),     src,     gk < P2_);
        cpa16(&BS_(st, nt_k, nt_n + 4), src + 4, gk < P2_);
    };

    loadB(0, 0); CPA_COMMIT();
    loadB(1, 16); CPA_COMMIT();

    for (int kt = 0; kt < KT; kt++) {
        if (kt + 1 < KT) { CPA_WAIT(1); } else { CPA_WAIT(0); }
        __syncthreads();
        int st = kt % 3;
        int kg = kt * 16;
#pragma unroll
        for (int ks = 0; ks < 16; ks += 8) {
            uint32_t af[4][4];
#pragma unroll
            for (int mt = 0; mt < 4; mt++) {
                int mrow = warp_m * 64 + mt * 16;
                af[mt][0] = __float_as_uint(SA_(mrow + g,     kg + ks + tq));
                af[mt][1] = __float_as_uint(SA_(mrow + g + 8, kg + ks + tq));
                af[mt][2] = __float_as_uint(SA_(mrow + g,     kg + ks + tq + 4));
                af[mt][3] = __float_as_uint(SA_(mrow + g + 8, kg + ks + tq + 4));
            }
            uint32_t bf[4][2];
#pragma unroll
            for (int nt = 0; nt < 4; nt++) {
                int ncol = warp_n * 32 + nt * 8 + g;
                bf[nt][0] = __float_as_uint(BS_(st, ks + tq,     ncol));
                bf[nt][1] = __float_as_uint(BS_(st, ks + tq + 4, ncol));
            }
#pragma unroll
            for (int mt = 0; mt < 4; mt++)
#pragma unroll
                for (int nt = 0; nt < 4; nt++)
                    mma_tf32(acc[mt][nt], af[mt], bf[nt]);
        }
        if (kt + 2 < KT) { loadB((kt + 2) % 3, (kt + 2) * 16); CPA_COMMIT(); }
    }

    // ---- epilogue: write T into g_u ----
    float* Cg = g_u + (size_t)bn * 128 * HID_;
#pragma unroll
    for (int mt = 0; mt < 4; mt++) {
        int row0 = warp_m * 64 + mt * 16 + g;
#pragma unroll
        for (int nt = 0; nt < 4; nt++) {
            int col = n0 + warp_n * 32 + nt * 8 + tq * 2;
#pragma unroll
            for (int half = 0; half < 2; half++) {
                int row = row0 + half * 8;
                Cg[(size_t)row * HID_ + col]     = acc[mt][nt][half * 2 + 0];
                Cg[(size_t)row * HID_ + col + 1] = acc[mt][nt][half * 2 + 1];
            }
        }
    }
#undef SA_
#undef BS_
}

// ---------------- tgt init ----------------
__global__ void init_tgt(const float* __restrict__ qe) {
    size_t i = (size_t)blockIdx.x * 256 + threadIdx.x;
    int c = (int)(i & 255);
    int m = (int)(i >> 8);
    int q = m & 15;
    g_tgt[i] = qe[q * HID_ + c];
}

// ---------------- self attention ----------------
__global__ __launch_bounds__(256) void self_attn() {
    int bn = blockIdx.x;
    __shared__ float sq[NQ_][260];
    __shared__ float sk[NQ_][260];
    __shared__ float sa[HEADS_][NQ_][NQ_ + 1];
    int t = threadIdx.x;
    const float* base = g_qkv + (size_t)bn * NQ_ * 768;
    for (int i = t; i < NQ_ * HID_; i += 256) {
        int q = i >> 8, c = i & 255;
        sq[q][c] = base[q * 768 + c];
        sk[q][c] = base[q * 768 + 256 + c];
    }
    __syncthreads();
    const float scale = 0.17677669529663687f;
    for (int i = t; i < HEADS_ * NQ_ * NQ_; i += 256) {
        int h = i >> 8, q = (i >> 4) & 15, kk = i & 15;
        float acc = 0.0f;
#pragma unroll
        for (int d = 0; d < DH_; d++) acc += sq[q][h * DH_ + d] * sk[kk][h * DH_ + d];
        sa[h][q][kk] = acc * scale;
    }
    __syncthreads();
    if (t < HEADS_ * NQ_) {
        int h = t >> 4, q = t & 15;
        float m = -FLT_MAX;
#pragma unroll
        for (int kk = 0; kk < NQ_; kk++) m = fmaxf(m, sa[h][q][kk]);
        float s = 0.0f;
#pragma unroll
        for (int kk = 0; kk < NQ_; kk++) { float e = expf(sa[h][q][kk] - m); sa[h][q][kk] = e; s += e; }
        float inv = 1.0f / s;
#pragma unroll
        for (int kk = 0; kk < NQ_; kk++) sa[h][q][kk] *= inv;
    }
    __syncthreads();
    float* out = g_ctx + (size_t)bn * NQ_ * HID_;
    for (int i = t; i < NQ_ * HID_; i += 256) {
        int q = i >> 8, c = i & 255;
        int h = c >> 5;
        float acc = 0.0f;
#pragma unroll
        for (int kk = 0; kk < NQ_; kk++) acc += sa[h][q][kk] * base[kk * 768 + 512 + c];
        out[q * HID_ + c] = acc;
    }
}

// ---------------- cross-attn U = Q_h @ Wk_h ----------------
__global__ __launch_bounds__(256) void cross_u(const float* __restrict__ Wk) {
    int h = blockIdx.x, bn = blockIdx.y;
    int c = threadIdx.x;
    __shared__ float sq[NQ_][DH_];
    for (int i = threadIdx.x; i < NQ_ * DH_; i += 256) {
        int q = i >> 5, d = i & 31;
        sq[q][d] = g_qc[((size_t)bn * NQ_ + q) * HID_ + h * DH_ + d];
    }
    __syncthreads();
    float acc[NQ_] = {};
#pragma unroll 4
    for (int d = 0; d < DH_; d++) {
        float w = Wk[(size_t)(h * DH_ + d) * HID_ + c];
#pragma unroll
        for (int q = 0; q < NQ_; q++) acc[q] += sq[q][d] * w;
    }
    float* dst = g_u + ((size_t)bn * 128 + h * NQ_) * HID_ + c;
#pragma unroll
    for (int q = 0; q < NQ_; q++) dst[(size_t)q * HID_] = acc[q];
}

// ---------------- cross-attn output: ctx = T @ Wv_h^T + bv ----------------
__global__ __launch_bounds__(512) void cross_o(const float* __restrict__ Wv,
                                               const float* __restrict__ bv) {
    int h = blockIdx.x, bn = blockIdx.y;
    __shared__ float ws[DH_][HID_ + 1];
    int t = threadIdx.x;
    for (int i = t; i < DH_ * HID_; i += 512) {
        int d = i >> 8, c = i & 255;
        ws[d][c] = Wv[(size_t)(h * DH_ + d) * HID_ + c];
    }
    __syncthreads();
    int q = t >> 5, d = t & 31;
    const float* trow = g_u + ((size_t)bn * 128 + h * NQ_ + q) * HID_;
    float acc = 0.0f;
#pragma unroll 4
    for (int c = 0; c < HID_; c += 4) {
        float4 tv = *reinterpret_cast<const float4*>(trow + c);
        acc += tv.x * ws[d][c] + tv.y * ws[d][c + 1] + tv.z * ws[d][c + 2] + tv.w * ws[d][c + 3];
    }
    g_ctx[((size_t)bn * NQ_ + q) * HID_ + h * DH_ + d] = acc + bv[h * DH_ + d];
}

// ---------------- layernorm ----------------
__global__ __launch_bounds__(256) void layernorm_k(const float* __restrict__ X,
                                                   const float* __restrict__ w,
                                                   const float* __restrict__ b,
                                                   float* __restrict__ Y) {
    int row = blockIdx.x * 8 + (threadIdx.x >> 5);
    int lane = threadIdx.x & 31;
    const float* x = X + (size_t)row * HID_;
    float v[8];
    float s = 0.0f;
#pragma unroll
    for (int i = 0; i < 8; i++) { v[i] = x[lane + i * 32]; s += v[i]; }
#pragma unroll
    for (int o = 16; o; o >>= 1) s += __shfl_xor_sync(0xffffffffu, s, o);
    float mu = s * (1.0f / 256.0f);
    float var = 0.0f;
#pragma unroll
    for (int i = 0; i < 8; i++) { float d = v[i] - mu; var += d * d; }
#pragma unroll
    for (int o = 16; o; o >>= 1) var += __shfl_xor_sync(0xffffffffu, var, o);
    var *= (1.0f / 256.0f);
    float r = rsqrtf(var + LN_EPS_);
    float* y = Y + (size_t)row * HID_;
#pragma unroll
    for (int i = 0; i < 8; i++) {
        int c = lane + i * 32;
        y[c] = (v[i] - mu) * r * w[c] + b[c];
    }
}

// ---------------- final head ----------------
__global__ __launch_bounds__(256) void final_out(const float* __restrict__ W,
                                                 const float* __restrict__ bias,
                                                 float* __restrict__ out) {
    int row = blockIdx.x * 8 + (threadIdx.x >> 5);
    int lane = threadIdx.x & 31;
    const float* x = g_tgt + (size_t)row * HID_;
    float acc[4] = {};
#pragma unroll
    for (int i = 0; i < 8; i++) {
        int c = lane + i * 32;
        float xv = x[c];
#pragma unroll
        for (int j = 0; j < 4; j++) acc[j] += xv * W[j * HID_ + c];
    }
#pragma unroll
    for (int j = 0; j < 4; j++)
#pragma unroll
        for (int o = 16; o; o >>= 1) acc[j] += __shfl_xor_sync(0xffffffffu, acc[j], o);
    if (lane < 4) out[(size_t)row * 4 + lane] = acc[lane] + bias[lane];
}

// ---------------- host ----------------
extern "C" void kernel_launch(void* const* d_in, const int* in_sizes, int n_in,
                              void* d_out, int out_size) {
    (void)in_sizes; (void)n_in; (void)out_size;
    const float* img         = (const float*)d_in[0];
    const float* kp          = (const float*)d_in[1];
    const unsigned char* msk = (const unsigned char*)d_in[2];
    const float* proj_w      = (const float*)d_in[3];
    const float* proj_b      = (const float*)d_in[4];
    const float* query_embed = (const float*)d_in[5];
    const float* self_qkv_w  = (const float*)d_in[6];
    const float* self_qkv_b  = (const float*)d_in[7];
    const float* self_out_w  = (const float*)d_in[8];
    const float* self_out_b  = (const float*)d_in[9];
    const float* cross_qkv_w = (const float*)d_in[10];
    const float* cross_qkv_b = (const float*)d_in[11];
    const float* cross_out_w = (const float*)d_in[12];
    const float* cross_out_b = (const float*)d_in[13];
    const float* ffn1_w      = (const float*)d_in[14];
    const float* ffn1_b      = (const float*)d_in[15];
    const float* ffn2_w      = (const float*)d_in[16];
    const float* ffn2_b      = (const float*)d_in[17];
    const float* ln1_w       = (const float*)d_in[18];
    const float* ln1_b       = (const float*)d_in[19];
    const float* ln2_w       = (const float*)d_in[20];
    const float* ln2_b       = (const float*)d_in[21];
    const float* ln3_w       = (const float*)d_in[22];
    const float* ln3_b       = (const float*)d_in[23];
    const float* out_w       = (const float*)d_in[24];
    const float* out_b       = (const float*)d_in[25];
    float* out = (float*)d_out;

    float *feat, *mem, *tgt, *y, *qkv, *ctx, *qc, *u, *s, *ffn;
    unsigned char* valid;
    cudaGetSymbolAddress((void**)&feat,  g_feat);
    cudaGetSymbolAddress((void**)&mem,   g_mem);
    cudaGetSymbolAddress((void**)&tgt,   g_tgt);
    cudaGetSymbolAddress((void**)&y,     g_y);
    cudaGetSymbolAddress((void**)&qkv,   g_qkv);
    cudaGetSymbolAddress((void**)&ctx,   g_ctx);
    cudaGetSymbolAddress((void**)&qc,    g_qc);
    cudaGetSymbolAddress((void**)&u,     g_u);
    cudaGetSymbolAddress((void**)&s,     g_s);
    cudaGetSymbolAddress((void**)&ffn,   g_ffn);
    cudaGetSymbolAddress((void**)&valid, g_valid);

    // opt-in smem (idempotent; legal host-side during capture)
    cudaFuncSetAttribute((const void*)gemm_tc<true,  false, false>,
                         cudaFuncAttributeMaxDynamicSharedMemorySize, GEMM_SMEM_);
    cudaFuncSetAttribute((const void*)gemm_tc<true,  true,  false>,
                         cudaFuncAttributeMaxDynamicSharedMemorySize, GEMM_SMEM_);
    cudaFuncSetAttribute((const void*)gemm_tc<false, false, false>,
                         cudaFuncAttributeMaxDynamicSharedMemorySize, GEMM_SMEM_);
    cudaFuncSetAttribute((const void*)gemm_tc<true,  false, true>,
                         cudaFuncAttributeMaxDynamicSharedMemorySize, GEMM_SMEM_);
    cudaFuncSetAttribute((const void*)attn_t,
                         cudaFuncAttributeMaxDynamicSharedMemorySize, ATTN_SMEM_);

    const float scale = 0.17677669529663687f;

    decode_mask<<<1, 512>>>(msk, valid);
    { dim3 g(WF_, HF_, B_); transpose_img<<<g, C_>>>(img); }
    { dim3 g(P2_, N_KP, B_); roi_gather<<<g, C_>>>(kp); }

    // mem = feat @ proj_w^T + proj_b
    gemm_tc<true, false, false><<<dim3(2, 900, 1), 256, GEMM_SMEM_>>>(
        feat, proj_w, proj_b, nullptr, mem, MMEM_, HID_, C_, C_, C_, HID_, 0, 0, 0, 1.0f);

    init_tgt<<<MROWS_, 256>>>(query_embed);

    for (int l = 0; l < DEPTH_; l++) {
        const float* sW  = self_qkv_w  + (size_t)l * 3 * HID_ * HID_;
        const float* sB  = self_qkv_b  + (size_t)l * 3 * HID_;
        const float* soW = self_out_w  + (size_t)l * HID_ * HID_;
        const float* soB = self_out_b  + (size_t)l * HID_;
        const float* cW  = cross_qkv_w + (size_t)l * 3 * HID_ * HID_;
        const float* cB  = cross_qkv_b + (size_t)l * 3 * HID_;
        const float* coW = cross_out_w + (size_t)l * HID_ * HID_;
        const float* coB = cross_out_b + (size_t)l * HID_;
        const float* f1W = ffn1_w + (size_t)l * FFN_ * HID_;
        const float* f1B = ffn1_b + (size_t)l * FFN_;
        const float* f2W = ffn2_w + (size_t)l * HID_ * FFN_;
        const float* f2B = ffn2_b + (size_t)l * HID_;

        // --- self attention ---
        gemm_tc<true, false, false><<<dim3(6, 64, 1), 256, GEMM_SMEM_>>>(
            tgt, sW, sB, nullptr, qkv, MROWS_, 3 * HID_, HID_, HID_, HID_, 3 * HID_, 0, 0, 0, 1.0f);
        self_attn<<<BN_, 256>>>();
        gemm_tc<true, true, false><<<dim3(2, 64, 1), 256, GEMM_SMEM_>>>(
            ctx, soW, soB, tgt, y, MROWS_, HID_, HID_, HID_, HID_, HID_, 0, 0, 0, 1.0f);
        layernorm_k<<<MROWS_ / 8, 256>>>(y, ln1_w + l * HID_, ln1_b + l * HID_, tgt);

        // --- cross attention (factored K/V) ---
        gemm_tc<true, false, false><<<dim3(2, 64, 1), 256, GEMM_SMEM_>>>(
            tgt, cW, cB, nullptr, qc, MROWS_, HID_, HID_, HID_, HID_, HID_, 0, 0, 0, 1.0f);
        { dim3 g(HEADS_, BN_); cross_u<<<g, 256>>>(cW + (size_t)HID_ * HID_); }
        // S = scale * U @ mem^T (raw scores, batched over bn)
        gemm_tc<false, false, false><<<dim3(2, 1, BN_), 256, GEMM_SMEM_>>>(
            u, mem, nullptr, nullptr, s, 128, P2_, HID_, HID_, HID_, SPAD_,
            (long long)128 * HID_, (long long)P2_ * HID_, (long long)128 * SPAD_, scale);
        // fused softmax + T = A @ mem
        attn_t<<<dim3(2, BN_), 256, ATTN_SMEM_>>>();
        { dim3 g(HEADS_, BN_); cross_o<<<g, 512>>>(cW + (size_t)2 * HID_ * HID_, cB + 2 * HID_); }
        gemm_tc<true, true, false><<<dim3(2, 64, 1), 256, GEMM_SMEM_>>>(
            ctx, coW, coB, tgt, y, MROWS_, HID_, HID_, HID_, HID_, HID_, 0, 0, 0, 1.0f);
        layernorm_k<<<MROWS_ / 8, 256>>>(y, ln2_w + l * HID_, ln2_b + l * HID_, tgt);

        // --- FFN ---
        gemm_tc<true, false, true><<<dim3(8, 64, 1), 256, GEMM_SMEM_>>>(
            tgt, f1W, f1B, nullptr, ffn, MROWS_, FFN_, HID_, HID_, HID_, FFN_, 0, 0, 0, 1.0f);
        gemm_tc<true, true, false><<<dim3(2, 64, 1), 256, GEMM_SMEM_>>>(
            ffn, f2W, f2B, tgt, y, MROWS_, HID_, FFN_, FFN_, FFN_, HID_, 0, 0, 0, 1.0f);
        layernorm_k<<<MROWS_ / 8, 256>>>(y, ln3_w + l * HID_, ln3_b + l * HID_, tgt);
    }

    final_out<<<MROWS_ / 8, 256>>>(out_w, out_b, out);
}

// round 6
// speedup vs baseline: 1.1372x; 1.1372x over previous
#include <cuda_runtime.h>
#include <math.h>
#include <float.h>
#include <stdint.h>

#define B_      2
#define N_KP    256
#define C_      256
#define HF_     64
#define WF_     64
#define ROI_    15
#define P2_     225
#define HID_    256
#define HEADS_  8
#define DH_     32
#define DEPTH_  3
#define FFN_    1024
#define NQ_     16
#define BN_     512          // B_*N_KP
#define MROWS_  8192         // BN_*NQ_
#define MMEM_   115200       // BN_*P2_
#define SPAD_   240          // padded S row; cols 225..239 zeroed by softmax
#define LN_EPS_ 1e-5f

#define GEMM_SMEM_  (2 * 3 * 128 * 20 * 4)     // 61440 B (A 7680 floats + B 7680 floats)

// ---------------- scratch ----------------
__device__ float g_imgT[(size_t)B_ * HF_ * WF_ * C_];
__device__ float g_feat[(size_t)MMEM_ * C_];
__device__ float g_mem [(size_t)MMEM_ * C_];
__device__ float g_tgt [(size_t)MROWS_ * HID_];
__device__ float g_y   [(size_t)MROWS_ * HID_];
__device__ float g_qkv [(size_t)MROWS_ * 3 * HID_];
__device__ float g_ctx [(size_t)MROWS_ * HID_];
__device__ float g_qc  [(size_t)MROWS_ * HID_];
__device__ float g_u   [(size_t)BN_ * 128 * HID_];
__device__ float g_s   [(size_t)BN_ * 128 * SPAD_];
__device__ float g_ffn [(size_t)MROWS_ * FFN_];
__device__ unsigned char g_valid[BN_];

// ---------------- helpers ----------------
__device__ __forceinline__ void mma_tf32(float* c, const uint32_t* a, const uint32_t* b) {
    asm volatile(
        "mma.sync.aligned.m16n8k8.row.col.f32.tf32.tf32.f32 "
        "{%0,%1,%2,%3}, {%4,%5,%6,%7}, {%8,%9}, {%0,%1,%2,%3};\n"
        : "+f"(c[0]), "+f"(c[1]), "+f"(c[2]), "+f"(c[3])
        : "r"(a[0]), "r"(a[1]), "r"(a[2]), "r"(a[3]), "r"(b[0]), "r"(b[1]));
}

__device__ __forceinline__ void ldsm4(uint32_t* r, uint32_t saddr) {
    asm volatile("ldmatrix.sync.aligned.m8n8.x4.shared.b16 {%0,%1,%2,%3}, [%4];\n"
                 : "=r"(r[0]), "=r"(r[1]), "=r"(r[2]), "=r"(r[3]) : "r"(saddr));
}

__device__ __forceinline__ void cpa16(void* smem_ptr, const void* gptr, bool pred) {
    uint32_t sa = (uint32_t)__cvta_generic_to_shared(smem_ptr);
    int sz = pred ? 16 : 0;
    asm volatile("cp.async.cg.shared.global [%0], [%1], 16, %2;\n"
                 :: "r"(sa), "l"(gptr), "r"(sz));
}
#define CPA_COMMIT() asm volatile("cp.async.commit_group;\n")
#define CPA_WAIT(n)  asm volatile("cp.async.wait_group %0;\n" :: "n"(n))

// ---------------- mask decode ----------------
__global__ void decode_mask(const unsigned char* __restrict__ m, unsigned char* __restrict__ out) {
    __shared__ int flag;
    if (threadIdx.x == 0) flag = 0;
    __syncthreads();
    int i = threadIdx.x;
    unsigned char v8 = m[i];
    if ((i & 3) != 0 && v8 != 0) atomicOr(&flag, 1);
    __syncthreads();
    if (flag) out[i] = (v8 != 0);
    else      out[i] = (((const int*)m)[i] != 0);
}

// ---------------- image transpose (B,C,H,W) -> (B,H,W,C) ----------------
__global__ void transpose_img(const float* __restrict__ img) {
    int x = blockIdx.x, y = blockIdx.y, b = blockIdx.z, c = threadIdx.x;
    g_imgT[(((size_t)b * HF_ + y) * WF_ + x) * C_ + c] =
        img[(((size_t)b * C_ + c) * HF_ + y) * WF_ + x];
}

// ---------------- ROI bilinear gather ----------------
__global__ __launch_bounds__(256) void roi_gather(const float* __restrict__ kp) {
    int p = blockIdx.x, n = blockIdx.y, b = blockIdx.z, c = threadIdx.x;
    int iy = p / ROI_, ix = p % ROI_;
    float rc0 = rintf(kp[((size_t)b * N_KP + n) * 2 + 0]);
    float rc1 = rintf(kp[((size_t)b * N_KP + n) * 2 + 1]);
    float gy = rc0 + (float)(iy - 7);
    float gx = rc1 + (float)(ix - 7);
    float gxn = __fdiv_rn(gx, 511.0f) * 2.0f - 1.0f;
    float gyn = __fdiv_rn(gy, 511.0f) * 2.0f - 1.0f;
    bool invalid = (gxn < -1.0f) || (gyn < -1.0f) || (gxn > 1.0f) || (gyn > 1.0f);
    float* dst = g_feat + ((size_t)((b * N_KP + n) * P2_ + p)) * C_;
    if (invalid) { dst[c] = 0.0f; return; }
    float x = ((gxn + 1.0f) * (float)WF_ - 1.0f) * 0.5f;
    float y = ((gyn + 1.0f) * (float)HF_ - 1.0f) * 0.5f;
    float x0f = floorf(x), y0f = floorf(y);
    float wx = x - x0f, wy = y - y0f;
    int x0 = (int)x0f, y0 = (int)y0f;
    int x1 = x0 + 1, y1 = y0 + 1;
    float w00 = (1.0f - wy) * (1.0f - wx);
    float w01 = (1.0f - wy) * wx;
    float w10 = wy * (1.0f - wx);
    float w11 = wy * wx;
    float acc = 0.0f;
    if (y0 >= 0 && y0 < HF_) {
        const float* rowp = g_imgT + ((size_t)(b * HF_ + y0) * WF_) * C_;
        if (x0 >= 0 && x0 < WF_) acc += w00 * rowp[(size_t)x0 * C_ + c];
        if (x1 >= 0 && x1 < WF_) acc += w01 * rowp[(size_t)x1 * C_ + c];
    }
    if (y1 >= 0 && y1 < HF_) {
        const float* rowp = g_imgT + ((size_t)(b * HF_ + y1) * WF_) * C_;
        if (x0 >= 0 && x0 < WF_) acc += w10 * rowp[(size_t)x0 * C_ + c];
        if (x1 >= 0 && x1 < WF_) acc += w11 * rowp[(size_t)x1 * C_ + c];
    }
    dst[c] = acc;
}

// ================= tf32 GEMM (ldmatrix + 3-stage cp.async) =================
// C = alpha * A @ op(B) [+ bias] [+ res] [relu]
// TB=true : B is (N,K) row-major.  TB=false : B is (K,N) row-major.
// Block 128x128, K-tile 16, 256 threads (8 warps 2Mx4N, warp tile 64x32).
// A (and TB B) staged [row][k] stride 20; fragments via ldmatrix.x4.
template<bool TB, bool HAS_BIAS, bool HAS_RES, bool RELU>
__global__ __launch_bounds__(256, 2) void gemm_tc(
    const float* __restrict__ A, const float* __restrict__ B,
    const float* __restrict__ bias, const float* __restrict__ Res,
    float* __restrict__ C,
    int M, int N, int K, int lda, int ldb, int ldc,
    long long sA, long long sB, long long sC, float alpha)
{
    extern __shared__ float dsm[];
    float* Asm = dsm;                    // [3][128][20]
    float* Bsm = dsm + 3 * 128 * 20;     // TB: [3][128][20]; NT: [3][16][136]
#define AS_(st,m,k)  Asm[(((st) * 128 + (m)) * 20) + (k)]
#define BT_(st,n,k)  Bsm[(((st) * 128 + (n)) * 20) + (k)]
#define BN_S(st,k,n) Bsm[(((st) * 16 + (k)) * 136) + (n)]

    long long z = blockIdx.z;
    A += z * sA; B += z * sB; C += z * sC;
    if (HAS_RES) Res += z * sC;

    int m0 = blockIdx.y * 128, n0 = blockIdx.x * 128;
    int t = threadIdx.x;
    int wid = t >> 5, lane = t & 31;
    int warp_m = wid >> 2;
    int warp_n = wid & 3;
    int g = lane >> 2, tq = lane & 3;

    int a_m0 = (t >> 2);
    int a_k  = (t & 3) * 4;
    int nt_k = t >> 4;
    int nt_n = (t & 15) * 8;

    // ldmatrix lane geometry
    int l7 = lane & 7;
    int gidx = lane >> 3;                       // 0..3
    int a_row_add = l7 + (gidx & 1) * 8;        // A: sub0/2 rows 0-7, sub1/3 rows 8-15
    int a_col_add = (gidx >> 1) * 4;            // A: sub0/1 k+0, sub2/3 k+4
    int b_row_add = l7 + (gidx >> 1) * 8;       // B: sub0/1 n 0-7, sub2/3 n 8-15
    int b_col_add = (gidx & 1) * 4;             // B: sub0/2 k+0, sub1/3 k+4

    uint32_t As_u = (uint32_t)__cvta_generic_to_shared(Asm);
    uint32_t Bs_u = (uint32_t)__cvta_generic_to_shared(Bsm);
    uint32_t a_lane = ((warp_m * 64 + a_row_add) * 20 + a_col_add) * 4;
    uint32_t b_lane = ((warp_n * 32 + b_row_add) * 20 + b_col_add) * 4;

    float acc[4][4][4];
#pragma unroll
    for (int i = 0; i < 4; i++)
#pragma unroll
        for (int j = 0; j < 4; j++)
#pragma unroll
            for (int r = 0; r < 4; r++) acc[i][j][r] = 0.0f;

    int KT = (K + 15) >> 4;

    auto load_tile = [&](int st, int k0) {
#pragma unroll
        for (int i = 0; i < 2; i++) {
            int m = a_m0 + i * 64;
            int gm = m0 + m, gk = k0 + a_k;
            cpa16(&AS_(st, m, a_k), A + (size_t)gm * lda + gk, gm < M);
        }
        if (TB) {
#pragma unroll
            for (int i = 0; i < 2; i++) {
                int n = a_m0 + i * 64;
                int gn = n0 + n, gk = k0 + a_k;
                cpa16(&BT_(st, n, a_k), B + (size_t)gn * ldb + gk, gn < N);
            }
        } else {
            int gk = k0 + nt_k;
            const float* src = B + (size_t)gk * ldb + n0 + nt_n;
            cpa16(&BN_S(st, nt_k, nt_n),     src,     gk < K);
            cpa16(&BN_S(st, nt_k, nt_n + 4), src + 4, gk < K);
        }
    };

    load_tile(0, 0); CPA_COMMIT();
    load_tile(1, 16); CPA_COMMIT();

    for (int kt = 0; kt < KT; kt++) {
        if (kt + 1 < KT) { CPA_WAIT(1); } else { CPA_WAIT(0); }
        __syncthreads();
        int st = kt % 3;
        uint32_t a_st = As_u + (uint32_t)(st * 128 * 20 * 4) + a_lane;
        uint32_t b_st = Bs_u + (uint32_t)(st * 128 * 20 * 4) + b_lane;
#pragma unroll
        for (int ks = 0; ks < 16; ks += 8) {
            uint32_t af[4][4];
#pragma unroll
            for (int mt = 0; mt < 4; mt++)
                ldsm4(af[mt], a_st + (uint32_t)((mt * 16 * 20 + ks) * 4));
            uint32_t bf[4][2];
            if (TB) {
#pragma unroll
                for (int p = 0; p < 2; p++) {
                    uint32_t tmp[4];
                    ldsm4(tmp, b_st + (uint32_t)((p * 16 * 20 + ks) * 4));
                    bf[2 * p][0] = tmp[0]; bf[2 * p][1] = tmp[1];
                    bf[2 * p + 1][0] = tmp[2]; bf[2 * p + 1][1] = tmp[3];
                }
            } else {
#pragma unroll
                for (int nt = 0; nt < 4; nt++) {
                    int ncol = warp_n * 32 + nt * 8 + g;
                    bf[nt][0] = __float_as_uint(BN_S(st, ks + tq,     ncol));
                    bf[nt][1] = __float_as_uint(BN_S(st, ks + tq + 4, ncol));
                }
            }
#pragma unroll
            for (int mt = 0; mt < 4; mt++)
#pragma unroll
                for (int nt = 0; nt < 4; nt++)
                    mma_tf32(acc[mt][nt], af[mt], bf[nt]);
        }
        if (kt + 2 < KT) { load_tile((kt + 2) % 3, (kt + 2) * 16); CPA_COMMIT(); }
    }

    // ---- epilogue ----
#pragma unroll
    for (int mt = 0; mt < 4; mt++) {
        int row0 = m0 + warp_m * 64 + mt * 16 + g;
#pragma unroll
        for (int nt = 0; nt < 4; nt++) {
            int col = n0 + warp_n * 32 + nt * 8 + tq * 2;
#pragma unroll
            for (int half = 0; half < 2; half++) {
                int row = row0 + half * 8;
                if (row >= M) continue;
                float v0 = acc[mt][nt][half * 2 + 0] * alpha;
                float v1 = acc[mt][nt][half * 2 + 1] * alpha;
                if (col < N) {
                    float v = v0;
                    if (HAS_BIAS) v += bias[col];
                    if (HAS_RES)  v += Res[(size_t)row * ldc + col];
                    if (RELU)     v = fmaxf(v, 0.0f);
                    C[(size_t)row * ldc + col] = v;
                }
                if (col + 1 < N) {
                    float v = v1;
                    if (HAS_BIAS) v += bias[col + 1];
                    if (HAS_RES)  v += Res[(size_t)row * ldc + col + 1];
                    if (RELU)     v = fmaxf(v, 0.0f);
                    C[(size_t)row * ldc + col + 1] = v;
                }
            }
        }
    }
#undef AS_
#undef BT_
#undef BN_S
}

// ---------------- tgt init ----------------
__global__ void init_tgt(const float* __restrict__ qe) {
    size_t i = (size_t)blockIdx.x * 256 + threadIdx.x;
    int c = (int)(i & 255);
    int m = (int)(i >> 8);
    int q = m & 15;
    g_tgt[i] = qe[q * HID_ + c];
}

// ---------------- self attention ----------------
__global__ __launch_bounds__(256) void self_attn() {
    int bn = blockIdx.x;
    __shared__ float sq[NQ_][260];
    __shared__ float sk[NQ_][260];
    __shared__ float sa[HEADS_][NQ_][NQ_ + 1];
    int t = threadIdx.x;
    const float* base = g_qkv + (size_t)bn * NQ_ * 768;
    for (int i = t; i < NQ_ * HID_; i += 256) {
        int q = i >> 8, c = i & 255;
        sq[q][c] = base[q * 768 + c];
        sk[q][c] = base[q * 768 + 256 + c];
    }
    __syncthreads();
    const float scale = 0.17677669529663687f;
    for (int i = t; i < HEADS_ * NQ_ * NQ_; i += 256) {
        int h = i >> 8, q = (i >> 4) & 15, kk = i & 15;
        float acc = 0.0f;
#pragma unroll
        for (int d = 0; d < DH_; d++) acc += sq[q][h * DH_ + d] * sk[kk][h * DH_ + d];
        sa[h][q][kk] = acc * scale;
    }
    __syncthreads();
    if (t < HEADS_ * NQ_) {
        int h = t >> 4, q = t & 15;
        float m = -FLT_MAX;
#pragma unroll
        for (int kk = 0; kk < NQ_; kk++) m = fmaxf(m, sa[h][q][kk]);
        float s = 0.0f;
#pragma unroll
        for (int kk = 0; kk < NQ_; kk++) { float e = expf(sa[h][q][kk] - m); sa[h][q][kk] = e; s += e; }
        float inv = 1.0f / s;
#pragma unroll
        for (int kk = 0; kk < NQ_; kk++) sa[h][q][kk] *= inv;
    }
    __syncthreads();
    float* out = g_ctx + (size_t)bn * NQ_ * HID_;
    for (int i = t; i < NQ_ * HID_; i += 256) {
        int q = i >> 8, c = i & 255;
        int h = c >> 5;
        float acc = 0.0f;
#pragma unroll
        for (int kk = 0; kk < NQ_; kk++) acc += sa[h][q][kk] * base[kk * 768 + 512 + c];
        out[q * HID_ + c] = acc;
    }
}

// ---------------- cross-attn U = Q_h @ Wk_h ----------------
__global__ __launch_bounds__(256) void cross_u(const float* __restrict__ Wk) {
    int h = blockIdx.x, bn = blockIdx.y;
    int c = threadIdx.x;
    __shared__ float sq[NQ_][DH_];
    for (int i = threadIdx.x; i < NQ_ * DH_; i += 256) {
        int q = i >> 5, d = i & 31;
        sq[q][d] = g_qc[((size_t)bn * NQ_ + q) * HID_ + h * DH_ + d];
    }
    __syncthreads();
    float acc[NQ_] = {};
#pragma unroll 4
    for (int d = 0; d < DH_; d++) {
        float w = Wk[(size_t)(h * DH_ + d) * HID_ + c];
#pragma unroll
        for (int q = 0; q < NQ_; q++) acc[q] += sq[q][d] * w;
    }
    float* dst = g_u + ((size_t)bn * 128 + h * NQ_) * HID_ + c;
#pragma unroll
    for (int q = 0; q < NQ_; q++) dst[(size_t)q * HID_] = acc[q];
}

// ---------------- masked softmax over 225 keys (+zero pad cols) ----------------
__global__ __launch_bounds__(256) void softmax_cross() {
    int row = blockIdx.x * 8 + (threadIdx.x >> 5);
    int lane = threadIdx.x & 31;
    int bn = row >> 7;
    bool v = g_valid[bn] != 0;
    float* s = g_s + (size_t)row * SPAD_;
    float vals[8];
    float m = -FLT_MAX;
#pragma unroll
    for (int i = 0; i < 8; i++) {
        int k = lane + i * 32;
        bool active = (k < P2_) && (v || k == 0);
        float x = active ? s[k] : -FLT_MAX;
        vals[i] = active ? x : -INFINITY;
        m = fmaxf(m, vals[i]);
    }
#pragma unroll
    for (int o = 16; o; o >>= 1) m = fmaxf(m, __shfl_xor_sync(0xffffffffu, m, o));
    float sum = 0.0f;
#pragma unroll
    for (int i = 0; i < 8; i++) {
        int k = lane + i * 32;
        bool active = (k < P2_) && (v || k == 0);
        float e = active ? expf(vals[i] - m) : 0.0f;
        vals[i] = e;
        sum += e;
    }
#pragma unroll
    for (int o = 16; o; o >>= 1) sum += __shfl_xor_sync(0xffffffffu, sum, o);
    float inv = 1.0f / sum;
#pragma unroll
    for (int i = 0; i < 8; i++) {
        int k = lane + i * 32;
        if (k < P2_)        s[k] = vals[i] * inv;
        else if (k < SPAD_) s[k] = 0.0f;
    }
}

// ---------------- cross-attn output: ctx = T @ Wv_h^T + bv ----------------
__global__ __launch_bounds__(512) void cross_o(const float* __restrict__ Wv,
                                               const float* __restrict__ bv) {
    int h = blockIdx.x, bn = blockIdx.y;
    __shared__ float ws[DH_][HID_ + 1];
    int t = threadIdx.x;
    for (int i = t; i < DH_ * HID_; i += 512) {
        int d = i >> 8, c = i & 255;
        ws[d][c] = Wv[(size_t)(h * DH_ + d) * HID_ + c];
    }
    __syncthreads();
    int q = t >> 5, d = t & 31;
    const float* trow = g_u + ((size_t)bn * 128 + h * NQ_ + q) * HID_;
    float acc = 0.0f;
#pragma unroll 4
    for (int c = 0; c < HID_; c += 4) {
        float4 tv = *reinterpret_cast<const float4*>(trow + c);
        acc += tv.x * ws[d][c] + tv.y * ws[d][c + 1] + tv.z * ws[d][c + 2] + tv.w * ws[d][c + 3];
    }
    g_ctx[((size_t)bn * NQ_ + q) * HID_ + h * DH_ + d] = acc + bv[h * DH_ + d];
}

// ---------------- layernorm ----------------
__global__ __launch_bounds__(256) void layernorm_k(const float* __restrict__ X,
                                                   const float* __restrict__ w,
                                                   const float* __restrict__ b,
                                                   float* __restrict__ Y) {
    int row = blockIdx.x * 8 + (threadIdx.x >> 5);
    int lane = threadIdx.x & 31;
    const float* x = X + (size_t)row * HID_;
    float v[8];
    float s = 0.0f;
#pragma unroll
    for (int i = 0; i < 8; i++) { v[i] = x[lane + i * 32]; s += v[i]; }
#pragma unroll
    for (int o = 16; o; o >>= 1) s += __shfl_xor_sync(0xffffffffu, s, o);
    float mu = s * (1.0f / 256.0f);
    float var = 0.0f;
#pragma unroll
    for (int i = 0; i < 8; i++) { float d = v[i] - mu; var += d * d; }
#pragma unroll
    for (int o = 16; o; o >>= 1) var += __shfl_xor_sync(0xffffffffu, var, o);
    var *= (1.0f / 256.0f);
    float r = rsqrtf(var + LN_EPS_);
    float* y = Y + (size_t)row * HID_;
#pragma unroll
    for (int i = 0; i < 8; i++) {
        int c = lane + i * 32;
        y[c] = (v[i] - mu) * r * w[c] + b[c];
    }
}

// ---------------- final head ----------------
__global__ __launch_bounds__(256) void final_out(const float* __restrict__ W,
                                                 const float* __restrict__ bias,
                                                 float* __restrict__ out) {
    int row = blockIdx.x * 8 + (threadIdx.x >> 5);
    int lane = threadIdx.x & 31;
    const float* x = g_tgt + (size_t)row * HID_;
    float acc[4] = {};
#pragma unroll
    for (int i = 0; i < 8; i++) {
        int c = lane + i * 32;
        float xv = x[c];
#pragma unroll
        for (int j = 0; j < 4; j++) acc[j] += xv * W[j * HID_ + c];
    }
#pragma unroll
    for (int j = 0; j < 4; j++)
#pragma unroll
        for (int o = 16; o; o >>= 1) acc[j] += __shfl_xor_sync(0xffffffffu, acc[j], o);
    if (lane < 4) out[(size_t)row * 4 + lane] = acc[lane] + bias[lane];
}

// ---------------- host ----------------
extern "C" void kernel_launch(void* const* d_in, const int* in_sizes, int n_in,
                              void* d_out, int out_size) {
    (void)in_sizes; (void)n_in; (void)out_size;
    const float* img         = (const float*)d_in[0];
    const float* kp          = (const float*)d_in[1];
    const unsigned char* msk = (const unsigned char*)d_in[2];
    const float* proj_w      = (const float*)d_in[3];
    const float* proj_b      = (const float*)d_in[4];
    const float* query_embed = (const float*)d_in[5];
    const float* self_qkv_w  = (const float*)d_in[6];
    const float* self_qkv_b  = (const float*)d_in[7];
    const float* self_out_w  = (const float*)d_in[8];
    const float* self_out_b  = (const float*)d_in[9];
    const float* cross_qkv_w = (const float*)d_in[10];
    const float* cross_qkv_b = (const float*)d_in[11];
    const float* cross_out_w = (const float*)d_in[12];
    const float* cross_out_b = (const float*)d_in[13];
    const float* ffn1_w      = (const float*)d_in[14];
    const float* ffn1_b      = (const float*)d_in[15];
    const float* ffn2_w      = (const float*)d_in[16];
    const float* ffn2_b      = (const float*)d_in[17];
    const float* ln1_w       = (const float*)d_in[18];
    const float* ln1_b       = (const float*)d_in[19];
    const float* ln2_w       = (const float*)d_in[20];
    const float* ln2_b       = (const float*)d_in[21];
    const float* ln3_w       = (const float*)d_in[22];
    const float* ln3_b       = (const float*)d_in[23];
    const float* out_w       = (const float*)d_in[24];
    const float* out_b       = (const float*)d_in[25];
    float* out = (float*)d_out;

    float *feat, *mem, *tgt, *y, *qkv, *ctx, *qc, *u, *s, *ffn;
    unsigned char* valid;
    cudaGetSymbolAddress((void**)&feat,  g_feat);
    cudaGetSymbolAddress((void**)&mem,   g_mem);
    cudaGetSymbolAddress((void**)&tgt,   g_tgt);
    cudaGetSymbolAddress((void**)&y,     g_y);
    cudaGetSymbolAddress((void**)&qkv,   g_qkv);
    cudaGetSymbolAddress((void**)&ctx,   g_ctx);
    cudaGetSymbolAddress((void**)&qc,    g_qc);
    cudaGetSymbolAddress((void**)&u,     g_u);
    cudaGetSymbolAddress((void**)&s,     g_s);
    cudaGetSymbolAddress((void**)&ffn,   g_ffn);
    cudaGetSymbolAddress((void**)&valid, g_valid);

    cudaFuncSetAttribute((const void*)gemm_tc<true,  true,  false, false>,
                         cudaFuncAttributeMaxDynamicSharedMemorySize, GEMM_SMEM_);
    cudaFuncSetAttribute((const void*)gemm_tc<true,  true,  true,  false>,
                         cudaFuncAttributeMaxDynamicSharedMemorySize, GEMM_SMEM_);
    cudaFuncSetAttribute((const void*)gemm_tc<true,  false, false, false>,
                         cudaFuncAttributeMaxDynamicSharedMemorySize, GEMM_SMEM_);
    cudaFuncSetAttribute((const void*)gemm_tc<true,  true,  false, true>,
                         cudaFuncAttributeMaxDynamicSharedMemorySize, GEMM_SMEM_);
    cudaFuncSetAttribute((const void*)gemm_tc<false, false, false, false>,
                         cudaFuncAttributeMaxDynamicSharedMemorySize, GEMM_SMEM_);

    const float scale = 0.17677669529663687f;

    decode_mask<<<1, 512>>>(msk, valid);
    { dim3 g(WF_, HF_, B_); transpose_img<<<g, C_>>>(img); }
    { dim3 g(P2_, N_KP, B_); roi_gather<<<g, C_>>>(kp); }

    // mem = feat @ proj_w^T + proj_b
    gemm_tc<true, true, false, false><<<dim3(2, 900, 1), 256, GEMM_SMEM_>>>(
        feat, proj_w, proj_b, nullptr, mem, MMEM_, HID_, C_, C_, C_, HID_, 0, 0, 0, 1.0f);

    init_tgt<<<MROWS_, 256>>>(query_embed);

    for (int l = 0; l < DEPTH_; l++) {
        const float* sW  = self_qkv_w  + (size_t)l * 3 * HID_ * HID_;
        const float* sB  = self_qkv_b  + (size_t)l * 3 * HID_;
        const float* soW = self_out_w  + (size_t)l * HID_ * HID_;
        const float* soB = self_out_b  + (size_t)l * HID_;
        const float* cW  = cross_qkv_w + (size_t)l * 3 * HID_ * HID_;
        const float* cB  = cross_qkv_b + (size_t)l * 3 * HID_;
        const float* coW = cross_out_w + (size_t)l * HID_ * HID_;
        const float* coB = cross_out_b + (size_t)l * HID_;
        const float* f1W = ffn1_w + (size_t)l * FFN_ * HID_;
        const float* f1B = ffn1_b + (size_t)l * FFN_;
        const float* f2W = ffn2_w + (size_t)l * HID_ * FFN_;
        const float* f2B = ffn2_b + (size_t)l * HID_;

        // --- self attention ---
        gemm_tc<true, true, false, false><<<dim3(6, 64, 1), 256, GEMM_SMEM_>>>(
            tgt, sW, sB, nullptr, qkv, MROWS_, 3 * HID_, HID_, HID_, HID_, 3 * HID_, 0, 0, 0, 1.0f);
        self_attn<<<BN_, 256>>>();
        gemm_tc<true, true, true, false><<<dim3(2, 64, 1), 256, GEMM_SMEM_>>>(
            ctx, soW, soB, tgt, y, MROWS_, HID_, HID_, HID_, HID_, HID_, 0, 0, 0, 1.0f);
        layernorm_k<<<MROWS_ / 8, 256>>>(y, ln1_w + l * HID_, ln1_b + l * HID_, tgt);

        // --- cross attention (factored K/V) ---
        gemm_tc<true, true, false, false><<<dim3(2, 64, 1), 256, GEMM_SMEM_>>>(
            tgt, cW, cB, nullptr, qc, MROWS_, HID_, HID_, HID_, HID_, HID_, 0, 0, 0, 1.0f);
        { dim3 g(HEADS_, BN_); cross_u<<<g, 256>>>(cW + (size_t)HID_ * HID_); }
        // S = scale * U @ mem^T (batched over bn)
        gemm_tc<true, false, false, false><<<dim3(2, 1, BN_), 256, GEMM_SMEM_>>>(
            u, mem, nullptr, nullptr, s, 128, P2_, HID_, HID_, HID_, SPAD_,
            (long long)128 * HID_, (long long)P2_ * HID_, (long long)128 * SPAD_, scale);
        softmax_cross<<<(BN_ * 128) / 8, 256>>>();
        // T = A @ mem (batched, NT) — K=225, pad cols of S are zero
        gemm_tc<false, false, false, false><<<dim3(2, 1, BN_), 256, GEMM_SMEM_>>>(
            s, mem, nullptr, nullptr, u, 128, HID_, P2_, SPAD_, HID_, HID_,
            (long long)128 * SPAD_, (long long)P2_ * HID_, (long long)128 * HID_, 1.0f);
        { dim3 g(HEADS_, BN_); cross_o<<<g, 512>>>(cW + (size_t)2 * HID_ * HID_, cB + 2 * HID_); }
        gemm_tc<true, true, true, false><<<dim3(2, 64, 1), 256, GEMM_SMEM_>>>(
            ctx, coW, coB, tgt, y, MROWS_, HID_, HID_, HID_, HID_, HID_, 0, 0, 0, 1.0f);
        layernorm_k<<<MROWS_ / 8, 256>>>(y, ln2_w + l * HID_, ln2_b + l * HID_, tgt);

        // --- FFN ---
        gemm_tc<true, true, false, true><<<dim3(8, 64, 1), 256, GEMM_SMEM_>>>(
            tgt, f1W, f1B, nullptr, ffn, MROWS_, FFN_, HID_, HID_, HID_, FFN_, 0, 0, 0, 1.0f);
        gemm_tc<true, true, true, false><<<dim3(2, 64, 1), 256, GEMM_SMEM_>>>(
            ffn, f2W, f2B, tgt, y, MROWS_, HID_, FFN_, FFN_, FFN_, HID_, 0, 0, 0, 1.0f);
        layernorm_k<<<MROWS_ / 8, 256>>>(y, ln3_w + l * HID_, ln3_b + l * HID_, tgt);
    }

    final_out<<<MROWS_ / 8, 256>>>(out_w, out_b, out);
}

// round 9
// speedup vs baseline: 1.1433x; 1.0054x over previous
#include <cuda_runtime.h>
#include <math.h>
#include <float.h>
#include <stdint.h>

#define B_      2
#define N_KP    256
#define C_      256
#define HF_     64
#define WF_     64
#define ROI_    15
#define P2_     225
#define HID_    256
#define HEADS_  8
#define DH_     32
#define DEPTH_  3
#define FFN_    1024
#define NQ_     16
#define BN_     512          // B_*N_KP
#define MROWS_  8192         // BN_*NQ_
#define MMEM_   115200       // BN_*P2_
#define SPAD_   240          // padded S row; cols 225..239 zeroed by softmax
#define LN_EPS_ 1e-5f

#define STAGES_     4
#define GEMM_SMEM_  (STAGES_ * 2 * 128 * 20 * 4)   // 81920 B

// ---------------- scratch ----------------
__device__ float g_imgT[(size_t)B_ * HF_ * WF_ * C_];
__device__ float g_feat[(size_t)MMEM_ * C_];
__device__ float g_mem [(size_t)MMEM_ * C_];
__device__ float g_tgt [(size_t)MROWS_ * HID_];
__device__ float g_y   [(size_t)MROWS_ * HID_];
__device__ float g_qkv [(size_t)MROWS_ * 3 * HID_];
__device__ float g_ctx [(size_t)MROWS_ * HID_];
__device__ float g_qc  [(size_t)MROWS_ * HID_];
__device__ float g_u   [(size_t)BN_ * 128 * HID_];
__device__ float g_s   [(size_t)BN_ * 128 * SPAD_];
__device__ float g_ffn [(size_t)MROWS_ * FFN_];
__device__ unsigned char g_valid[BN_];

// ---------------- helpers ----------------
__device__ __forceinline__ void mma_tf32(float* c, const uint32_t* a, const uint32_t* b) {
    asm volatile(
        "mma.sync.aligned.m16n8k8.row.col.f32.tf32.tf32.f32 "
        "{%0,%1,%2,%3}, {%4,%5,%6,%7}, {%8,%9}, {%0,%1,%2,%3};\n"
        : "+f"(c[0]), "+f"(c[1]), "+f"(c[2]), "+f"(c[3])
        : "r"(a[0]), "r"(a[1]), "r"(a[2]), "r"(a[3]), "r"(b[0]), "r"(b[1]));
}

__device__ __forceinline__ void ldsm4(uint32_t* r, uint32_t saddr) {
    asm volatile("ldmatrix.sync.aligned.m8n8.x4.shared.b16 {%0,%1,%2,%3}, [%4];\n"
                 : "=r"(r[0]), "=r"(r[1]), "=r"(r[2]), "=r"(r[3]) : "r"(saddr));
}

__device__ __forceinline__ void cpa16(void* smem_ptr, const void* gptr, bool pred) {
    uint32_t sa = (uint32_t)__cvta_generic_to_shared(smem_ptr);
    int sz = pred ? 16 : 0;
    asm volatile("cp.async.cg.shared.global [%0], [%1], 16, %2;\n"
                 :: "r"(sa), "l"(gptr), "r"(sz));
}
#define CPA_COMMIT() asm volatile("cp.async.commit_group;\n")
#define CPA_WAIT(n)  asm volatile("cp.async.wait_group %0;\n" :: "n"(n))

// ---------------- mask decode ----------------
__global__ void decode_mask(const unsigned char* __restrict__ m, unsigned char* __restrict__ out) {
    __shared__ int flag;
    if (threadIdx.x == 0) flag = 0;
    __syncthreads();
    int i = threadIdx.x;
    unsigned char v8 = m[i];
    if ((i & 3) != 0 && v8 != 0) atomicOr(&flag, 1);
    __syncthreads();
    if (flag) out[i] = (v8 != 0);
    else      out[i] = (((const int*)m)[i] != 0);
}

// ---------------- image transpose (B,C,H,W) -> (B,H,W,C) ----------------
__global__ void transpose_img(const float* __restrict__ img) {
    int x = blockIdx.x, y = blockIdx.y, b = blockIdx.z, c = threadIdx.x;
    g_imgT[(((size_t)b * HF_ + y) * WF_ + x) * C_ + c] =
        img[(((size_t)b * C_ + c) * HF_ + y) * WF_ + x];
}

// ---------------- ROI bilinear gather ----------------
__global__ __launch_bounds__(256) void roi_gather(const float* __restrict__ kp) {
    int p = blockIdx.x, n = blockIdx.y, b = blockIdx.z, c = threadIdx.x;
    int iy = p / ROI_, ix = p % ROI_;
    float rc0 = rintf(kp[((size_t)b * N_KP + n) * 2 + 0]);
    float rc1 = rintf(kp[((size_t)b * N_KP + n) * 2 + 1]);
    float gy = rc0 + (float)(iy - 7);
    float gx = rc1 + (float)(ix - 7);
    float gxn = __fdiv_rn(gx, 511.0f) * 2.0f - 1.0f;
    float gyn = __fdiv_rn(gy, 511.0f) * 2.0f - 1.0f;
    bool invalid = (gxn < -1.0f) || (gyn < -1.0f) || (gxn > 1.0f) || (gyn > 1.0f);
    float* dst = g_feat + ((size_t)((b * N_KP + n) * P2_ + p)) * C_;
    if (invalid) { dst[c] = 0.0f; return; }
    float x = ((gxn + 1.0f) * (float)WF_ - 1.0f) * 0.5f;
    float y = ((gyn + 1.0f) * (float)HF_ - 1.0f) * 0.5f;
    float x0f = floorf(x), y0f = floorf(y);
    float wx = x - x0f, wy = y - y0f;
    int x0 = (int)x0f, y0 = (int)y0f;
    int x1 = x0 + 1, y1 = y0 + 1;
    float w00 = (1.0f - wy) * (1.0f - wx);
    float w01 = (1.0f - wy) * wx;
    float w10 = wy * (1.0f - wx);
    float w11 = wy * wx;
    float acc = 0.0f;
    if (y0 >= 0 && y0 < HF_) {
        const float* rowp = g_imgT + ((size_t)(b * HF_ + y0) * WF_) * C_;
        if (x0 >= 0 && x0 < WF_) acc += w00 * rowp[(size_t)x0 * C_ + c];
        if (x1 >= 0 && x1 < WF_) acc += w01 * rowp[(size_t)x1 * C_ + c];
    }
    if (y1 >= 0 && y1 < HF_) {
        const float* rowp = g_imgT + ((size_t)(b * HF_ + y1) * WF_) * C_;
        if (x0 >= 0 && x0 < WF_) acc += w10 * rowp[(size_t)x0 * C_ + c];
        if (x1 >= 0 && x1 < WF_) acc += w11 * rowp[(size_t)x1 * C_ + c];
    }
    dst[c] = acc;
}

// ================= tf32 GEMM (ldmatrix + 4-stage cp.async, K-tile 16) =================
// C = alpha * A @ op(B) [+ bias] [+ res] [relu]
// TB=true : B is (N,K) row-major.  TB=false : B is (K,N) row-major.
// Block 128x128, K-tile 16, 256 threads (8 warps 2Mx4N, warp tile 64x32).
// A (and TB B) staged [row][k] stride 20; fragments via ldmatrix.x4.
template<bool TB, bool HAS_BIAS, bool HAS_RES, bool RELU>
__global__ __launch_bounds__(256, 2) void gemm_tc(
    const float* __restrict__ A, const float* __restrict__ B,
    const float* __restrict__ bias, const float* __restrict__ Res,
    float* __restrict__ C,
    int M, int N, int K, int lda, int ldb, int ldc,
    long long sA, long long sB, long long sC, float alpha)
{
    extern __shared__ float dsm[];
    float* Asm = dsm;                          // [STAGES_][128][20]
    float* Bsm = dsm + STAGES_ * 128 * 20;     // TB: [STAGES_][128][20]; NT: [STAGES_][16][136]
#define AS_(st,m,k)  Asm[(((st) * 128 + (m)) * 20) + (k)]
#define BT_(st,n,k)  Bsm[(((st) * 128 + (n)) * 20) + (k)]
#define BN_S(st,k,n) Bsm[(((st) * 16 + (k)) * 136) + (n)]

    long long z = blockIdx.z;
    A += z * sA; B += z * sB; C += z * sC;
    if (HAS_RES) Res += z * sC;

    int m0 = blockIdx.y * 128, n0 = blockIdx.x * 128;
    int t = threadIdx.x;
    int wid = t >> 5, lane = t & 31;
    int warp_m = wid >> 2;
    int warp_n = wid & 3;
    int g = lane >> 2, tq = lane & 3;

    int a_m0 = (t >> 2);
    int a_k  = (t & 3) * 4;
    int nt_k = t >> 4;
    int nt_n = (t & 15) * 8;

    // ldmatrix lane geometry
    int l7 = lane & 7;
    int gidx = lane >> 3;
    int a_row_add = l7 + (gidx & 1) * 8;
    int a_col_add = (gidx >> 1) * 4;
    int b_row_add = l7 + (gidx >> 1) * 8;
    int b_col_add = (gidx & 1) * 4;

    uint32_t As_u = (uint32_t)__cvta_generic_to_shared(Asm);
    uint32_t Bs_u = (uint32_t)__cvta_generic_to_shared(Bsm);
    uint32_t a_lane = ((warp_m * 64 + a_row_add) * 20 + a_col_add) * 4;
    uint32_t b_lane = ((warp_n * 32 + b_row_add) * 20 + b_col_add) * 4;

    float acc[4][4][4];
#pragma unroll
    for (int i = 0; i < 4; i++)
#pragma unroll
        for (int j = 0; j < 4; j++)
#pragma unroll
            for (int r = 0; r < 4; r++) acc[i][j][r] = 0.0f;

    int KT = (K + 15) >> 4;

    auto load_tile = [&](int st, int k0) {
#pragma unroll
        for (int i = 0; i < 2; i++) {
            int m = a_m0 + i * 64;
            int gm = m0 + m, gk = k0 + a_k;
            cpa16(&AS_(st, m, a_k), A + (size_t)gm * lda + gk, gm < M);
        }
        if (TB) {
#pragma unroll
            for (int i = 0; i < 2; i++) {
                int n = a_m0 + i * 64;
                int gn = n0 + n, gk = k0 + a_k;
                cpa16(&BT_(st, n, a_k), B + (size_t)gn * ldb + gk, gn < N);
            }
        } else {
            int gk = k0 + nt_k;
            const float* src = B + (size_t)gk * ldb + n0 + nt_n;
            cpa16(&BN_S(st, nt_k, nt_n),     src,     gk < K);
            cpa16(&BN_S(st, nt_k, nt_n + 4), src + 4, gk < K);
        }
    };

    load_tile(0, 0); CPA_COMMIT();
    if (1 < KT) { load_tile(1, 16); CPA_COMMIT(); }
    if (2 < KT) { load_tile(2, 32); CPA_COMMIT(); }

    for (int kt = 0; kt < KT; kt++) {
        if (kt + 2 < KT)      { CPA_WAIT(2); }
        else if (kt + 1 < KT) { CPA_WAIT(1); }
        else                  { CPA_WAIT(0); }
        __syncthreads();
        // early prefetch: stage (kt+3)&3 was tile kt-1's buffer; the barrier
        // above proves all warps finished tile kt-1, so overwriting is safe.
        if (kt + 3 < KT) { load_tile((kt + 3) & 3, (kt + 3) * 16); CPA_COMMIT(); }

        int st = kt & 3;
        uint32_t a_st = As_u + (uint32_t)(st * 128 * 20 * 4) + a_lane;
        uint32_t b_st = Bs_u + (uint32_t)(st * 128 * 20 * 4) + b_lane;
#pragma unroll
        for (int ks = 0; ks < 16; ks += 8) {
            uint32_t af[4][4];
#pragma unroll
            for (int mt = 0; mt < 4; mt++)
                ldsm4(af[mt], a_st + (uint32_t)((mt * 16 * 20 + ks) * 4));
            uint32_t bf[4][2];
            if (TB) {
#pragma unroll
                for (int p = 0; p < 2; p++) {
                    uint32_t tmp[4];
                    ldsm4(tmp, b_st + (uint32_t)((p * 16 * 20 + ks) * 4));
                    bf[2 * p][0] = tmp[0]; bf[2 * p][1] = tmp[1];
                    bf[2 * p + 1][0] = tmp[2]; bf[2 * p + 1][1] = tmp[3];
                }
            } else {
#pragma unroll
                for (int nt = 0; nt < 4; nt++) {
                    int ncol = warp_n * 32 + nt * 8 + g;
                    bf[nt][0] = __float_as_uint(BN_S(st, ks + tq,     ncol));
                    bf[nt][1] = __float_as_uint(BN_S(st, ks + tq + 4, ncol));
                }
            }
#pragma unroll
            for (int mt = 0; mt < 4; mt++)
#pragma unroll
                for (int nt = 0; nt < 4; nt++)
                    mma_tf32(acc[mt][nt], af[mt], bf[nt]);
        }
    }

    // ---- epilogue ----
#pragma unroll
    for (int mt = 0; mt < 4; mt++) {
        int row0 = m0 + warp_m * 64 + mt * 16 + g;
#pragma unroll
        for (int nt = 0; nt < 4; nt++) {
            int col = n0 + warp_n * 32 + nt * 8 + tq * 2;
#pragma unroll
            for (int half = 0; half < 2; half++) {
                int row = row0 + half * 8;
                if (row >= M) continue;
                float v0 = acc[mt][nt][half * 2 + 0] * alpha;
                float v1 = acc[mt][nt][half * 2 + 1] * alpha;
                if (col < N) {
                    float v = v0;
                    if (HAS_BIAS) v += bias[col];
                    if (HAS_RES)  v += Res[(size_t)row * ldc + col];
                    if (RELU)     v = fmaxf(v, 0.0f);
                    C[(size_t)row * ldc + col] = v;
                }
                if (col + 1 < N) {
                    float v = v1;
                    if (HAS_BIAS) v += bias[col + 1];
                    if (HAS_RES)  v += Res[(size_t)row * ldc + col + 1];
                    if (RELU)     v = fmaxf(v, 0.0f);
                    C[(size_t)row * ldc + col + 1] = v;
                }
            }
        }
    }
#undef AS_
#undef BT_
#undef BN_S
}

// ---------------- tgt init ----------------
__global__ void init_tgt(const float* __restrict__ qe) {
    size_t i = (size_t)blockIdx.x * 256 + threadIdx.x;
    int c = (int)(i & 255);
    int m = (int)(i >> 8);
    int q = m & 15;
    g_tgt[i] = qe[q * HID_ + c];
}

// ---------------- self attention ----------------
__global__ __launch_bounds__(256) void self_attn() {
    int bn = blockIdx.x;
    __shared__ float sq[NQ_][260];
    __shared__ float sk[NQ_][260];
    __shared__ float sa[HEADS_][NQ_][NQ_ + 1];
    int t = threadIdx.x;
    const float* base = g_qkv + (size_t)bn * NQ_ * 768;
    for (int i = t; i < NQ_ * HID_; i += 256) {
        int q = i >> 8, c = i & 255;
        sq[q][c] = base[q * 768 + c];
        sk[q][c] = base[q * 768 + 256 + c];
    }
    __syncthreads();
    const float scale = 0.17677669529663687f;
    for (int i = t; i < HEADS_ * NQ_ * NQ_; i += 256) {
        int h = i >> 8, q = (i >> 4) & 15, kk = i & 15;
        float acc = 0.0f;
#pragma unroll
        for (int d = 0; d < DH_; d++) acc += sq[q][h * DH_ + d] * sk[kk][h * DH_ + d];
        sa[h][q][kk] = acc * scale;
    }
    __syncthreads();
    if (t < HEADS_ * NQ_) {
        int h = t >> 4, q = t & 15;
        float m = -FLT_MAX;
#pragma unroll
        for (int kk = 0; kk < NQ_; kk++) m = fmaxf(m, sa[h][q][kk]);
        float s = 0.0f;
#pragma unroll
        for (int kk = 0; kk < NQ_; kk++) { float e = expf(sa[h][q][kk] - m); sa[h][q][kk] = e; s += e; }
        float inv = 1.0f / s;
#pragma unroll
        for (int kk = 0; kk < NQ_; kk++) sa[h][q][kk] *= inv;
    }
    __syncthreads();
    float* out = g_ctx + (size_t)bn * NQ_ * HID_;
    for (int i = t; i < NQ_ * HID_; i += 256) {
        int q = i >> 8, c = i & 255;
        int h = c >> 5;
        float acc = 0.0f;
#pragma unroll
        for (int kk = 0; kk < NQ_; kk++) acc += sa[h][q][kk] * base[kk * 768 + 512 + c];
        out[q * HID_ + c] = acc;
    }
}

// ---------------- cross-attn U = Q_h @ Wk_h ----------------
__global__ __launch_bounds__(256) void cross_u(const float* __restrict__ Wk) {
    int h = blockIdx.x, bn = blockIdx.y;
    int c = threadIdx.x;
    __shared__ float sq[NQ_][DH_];
    for (int i = threadIdx.x; i < NQ_ * DH_; i += 256) {
        int q = i >> 5, d = i & 31;
        sq[q][d] = g_qc[((size_t)bn * NQ_ + q) * HID_ + h * DH_ + d];
    }
    __syncthreads();
    float acc[NQ_] = {};
#pragma unroll 4
    for (int d = 0; d < DH_; d++) {
        float w = Wk[(size_t)(h * DH_ + d) * HID_ + c];
#pragma unroll
        for (int q = 0; q < NQ_; q++) acc[q] += sq[q][d] * w;
    }
    float* dst = g_u + ((size_t)bn * 128 + h * NQ_) * HID_ + c;
#pragma unroll
    for (int q = 0; q < NQ_; q++) dst[(size_t)q * HID_] = acc[q];
}

// ---------------- masked softmax over 225 keys (+zero pad cols) ----------------
__global__ __launch_bounds__(256) void softmax_cross() {
    int row = blockIdx.x * 8 + (threadIdx.x >> 5);
    int lane = threadIdx.x & 31;
    int bn = row >> 7;
    bool v = g_valid[bn] != 0;
    float* s = g_s + (size_t)row * SPAD_;
    float vals[8];
    float m = -FLT_MAX;
#pragma unroll
    for (int i = 0; i < 8; i++) {
        int k = lane + i * 32;
        bool active = (k < P2_) && (v || k == 0);
        float x = active ? s[k] : -FLT_MAX;
        vals[i] = active ? x : -INFINITY;
        m = fmaxf(m, vals[i]);
    }
#pragma unroll
    for (int o = 16; o; o >>= 1) m = fmaxf(m, __shfl_xor_sync(0xffffffffu, m, o));
    float sum = 0.0f;
#pragma unroll
    for (int i = 0; i < 8; i++) {
        int k = lane + i * 32;
        bool active = (k < P2_) && (v || k == 0);
        float e = active ? expf(vals[i] - m) : 0.0f;
        vals[i] = e;
        sum += e;
    }
#pragma unroll
    for (int o = 16; o; o >>= 1) sum += __shfl_xor_sync(0xffffffffu, sum, o);
    float inv = 1.0f / sum;
#pragma unroll
    for (int i = 0; i < 8; i++) {
        int k = lane + i * 32;
        if (k < P2_)        s[k] = vals[i] * inv;
        else if (k < SPAD_) s[k] = 0.0f;
    }
}

// ---------------- cross-attn output: ctx = T @ Wv_h^T + bv ----------------
__global__ __launch_bounds__(512) void cross_o(const float* __restrict__ Wv,
                                               const float* __restrict__ bv) {
    int h = blockIdx.x, bn = blockIdx.y;
    __shared__ float ws[DH_][HID_ + 1];
    int t = threadIdx.x;
    for (int i = t; i < DH_ * HID_; i += 512) {
        int d = i >> 8, c = i & 255;
        ws[d][c] = Wv[(size_t)(h * DH_ + d) * HID_ + c];
    }
    __syncthreads();
    int q = t >> 5, d = t & 31;
    const float* trow = g_u + ((size_t)bn * 128 + h * NQ_ + q) * HID_;
    float acc = 0.0f;
#pragma unroll 4
    for (int c = 0; c < HID_; c += 4) {
        float4 tv = *reinterpret_cast<const float4*>(trow + c);
        acc += tv.x * ws[d][c] + tv.y * ws[d][c + 1] + tv.z * ws[d][c + 2] + tv.w * ws[d][c + 3];
    }
    g_ctx[((size_t)bn * NQ_ + q) * HID_ + h * DH_ + d] = acc + bv[h * DH_ + d];
}

// ---------------- layernorm ----------------
__global__ __launch_bounds__(256) void layernorm_k(const float* __restrict__ X,
                                                   const float* __restrict__ w,
                                                   const float* __restrict__ b,
                                                   float* __restrict__ Y) {
    int row = blockIdx.x * 8 + (threadIdx.x >> 5);
    int lane = threadIdx.x & 31;
    const float* x = X + (size_t)row * HID_;
    float v[8];
    float s = 0.0f;
#pragma unroll
    for (int i = 0; i < 8; i++) { v[i] = x[lane + i * 32]; s += v[i]; }
#pragma unroll
    for (int o = 16; o; o >>= 1) s += __shfl_xor_sync(0xffffffffu, s, o);
    float mu = s * (1.0f / 256.0f);
    float var = 0.0f;
#pragma unroll
    for (int i = 0; i < 8; i++) { float d = v[i] - mu; var += d * d; }
#pragma unroll
    for (int o = 16; o; o >>= 1) var += __shfl_xor_sync(0xffffffffu, var, o);
    var *= (1.0f / 256.0f);
    float r = rsqrtf(var + LN_EPS_);
    float* y = Y + (size_t)row * HID_;
#pragma unroll
    for (int i = 0; i < 8; i++) {
        int c = lane + i * 32;
        y[c] = (v[i] - mu) * r * w[c] + b[c];
    }
}

// ---------------- final head ----------------
__global__ __launch_bounds__(256) void final_out(const float* __restrict__ W,
                                                 const float* __restrict__ bias,
                                                 float* __restrict__ out) {
    int row = blockIdx.x * 8 + (threadIdx.x >> 5);
    int lane = threadIdx.x & 31;
    const float* x = g_tgt + (size_t)row * HID_;
    float acc[4] = {};
#pragma unroll
    for (int i = 0; i < 8; i++) {
        int c = lane + i * 32;
        float xv = x[c];
#pragma unroll
        for (int j = 0; j < 4; j++) acc[j] += xv * W[j * HID_ + c];
    }
#pragma unroll
    for (int j = 0; j < 4; j++)
#pragma unroll
        for (int o = 16; o; o >>= 1) acc[j] += __shfl_xor_sync(0xffffffffu, acc[j], o);
    if (lane < 4) out[(size_t)row * 4 + lane] = acc[lane] + bias[lane];
}

// ---------------- host ----------------
extern "C" void kernel_launch(void* const* d_in, const int* in_sizes, int n_in,
                              void* d_out, int out_size) {
    (void)in_sizes; (void)n_in; (void)out_size;
    const float* img         = (const float*)d_in[0];
    const float* kp          = (const float*)d_in[1];
    const unsigned char* msk = (const unsigned char*)d_in[2];
    const float* proj_w      = (const float*)d_in[3];
    const float* proj_b      = (const float*)d_in[4];
    const float* query_embed = (const float*)d_in[5];
    const float* self_qkv_w  = (const float*)d_in[6];
    const float* self_qkv_b  = (const float*)d_in[7];
    const float* self_out_w  = (const float*)d_in[8];
    const float* self_out_b  = (const float*)d_in[9];
    const float* cross_qkv_w = (const float*)d_in[10];
    const float* cross_qkv_b = (const float*)d_in[11];
    const float* cross_out_w = (const float*)d_in[12];
    const float* cross_out_b = (const float*)d_in[13];
    const float* ffn1_w      = (const float*)d_in[14];
    const float* ffn1_b      = (const float*)d_in[15];
    const float* ffn2_w      = (const float*)d_in[16];
    const float* ffn2_b      = (const float*)d_in[17];
    const float* ln1_w       = (const float*)d_in[18];
    const float* ln1_b       = (const float*)d_in[19];
    const float* ln2_w       = (const float*)d_in[20];
    const float* ln2_b       = (const float*)d_in[21];
    const float* ln3_w       = (const float*)d_in[22];
    const float* ln3_b       = (const float*)d_in[23];
    const float* out_w       = (const float*)d_in[24];
    const float* out_b       = (const float*)d_in[25];
    float* out = (float*)d_out;

    float *feat, *mem, *tgt, *y, *qkv, *ctx, *qc, *u, *s, *ffn;
    unsigned char* valid;
    cudaGetSymbolAddress((void**)&feat,  g_feat);
    cudaGetSymbolAddress((void**)&mem,   g_mem);
    cudaGetSymbolAddress((void**)&tgt,   g_tgt);
    cudaGetSymbolAddress((void**)&y,     g_y);
    cudaGetSymbolAddress((void**)&qkv,   g_qkv);
    cudaGetSymbolAddress((void**)&ctx,   g_ctx);
    cudaGetSymbolAddress((void**)&qc,    g_qc);
    cudaGetSymbolAddress((void**)&u,     g_u);
    cudaGetSymbolAddress((void**)&s,     g_s);
    cudaGetSymbolAddress((void**)&ffn,   g_ffn);
    cudaGetSymbolAddress((void**)&valid, g_valid);

    cudaFuncSetAttribute((const void*)gemm_tc<true,  true,  false, false>,
                         cudaFuncAttributeMaxDynamicSharedMemorySize, GEMM_SMEM_);
    cudaFuncSetAttribute((const void*)gemm_tc<true,  true,  true,  false>,
                         cudaFuncAttributeMaxDynamicSharedMemorySize, GEMM_SMEM_);
    cudaFuncSetAttribute((const void*)gemm_tc<true,  false, false, false>,
                         cudaFuncAttributeMaxDynamicSharedMemorySize, GEMM_SMEM_);
    cudaFuncSetAttribute((const void*)gemm_tc<true,  true,  false, true>,
                         cudaFuncAttributeMaxDynamicSharedMemorySize, GEMM_SMEM_);
    cudaFuncSetAttribute((const void*)gemm_tc<false, false, false, false>,
                         cudaFuncAttributeMaxDynamicSharedMemorySize, GEMM_SMEM_);

    const float scale = 0.17677669529663687f;

    decode_mask<<<1, 512>>>(msk, valid);
    { dim3 g(WF_, HF_, B_); transpose_img<<<g, C_>>>(img); }
    { dim3 g(P2_, N_KP, B_); roi_gather<<<g, C_>>>(kp); }

    // mem = feat @ proj_w^T + proj_b
    gemm_tc<true, true, false, false><<<dim3(2, 900, 1), 256, GEMM_SMEM_>>>(
        feat, proj_w, proj_b, nullptr, mem, MMEM_, HID_, C_, C_, C_, HID_, 0, 0, 0, 1.0f);

    init_tgt<<<MROWS_, 256>>>(query_embed);

    for (int l = 0; l < DEPTH_; l++) {
        const float* sW  = self_qkv_w  + (size_t)l * 3 * HID_ * HID_;
        const float* sB  = self_qkv_b  + (size_t)l * 3 * HID_;
        const float* soW = self_out_w  + (size_t)l * HID_ * HID_;
        const float* soB = self_out_b  + (size_t)l * HID_;
        const float* cW  = cross_qkv_w + (size_t)l * 3 * HID_ * HID_;
        const float* cB  = cross_qkv_b + (size_t)l * 3 * HID_;
        const float* coW = cross_out_w + (size_t)l * HID_ * HID_;
        const float* coB = cross_out_b + (size_t)l * HID_;
        const float* f1W = ffn1_w + (size_t)l * FFN_ * HID_;
        const float* f1B = ffn1_b + (size_t)l * FFN_;
        const float* f2W = ffn2_w + (size_t)l * HID_ * FFN_;
        const float* f2B = ffn2_b + (size_t)l * HID_;

        // --- self attention ---
        gemm_tc<true, true, false, false><<<dim3(6, 64, 1), 256, GEMM_SMEM_>>>(
            tgt, sW, sB, nullptr, qkv, MROWS_, 3 * HID_, HID_, HID_, HID_, 3 * HID_, 0, 0, 0, 1.0f);
        self_attn<<<BN_, 256>>>();
        gemm_tc<true, true, true, false><<<dim3(2, 64, 1), 256, GEMM_SMEM_>>>(
            ctx, soW, soB, tgt, y, MROWS_, HID_, HID_, HID_, HID_, HID_, 0, 0, 0, 1.0f);
        layernorm_k<<<MROWS_ / 8, 256>>>(y, ln1_w + l * HID_, ln1_b + l * HID_, tgt);

        // --- cross attention (factored K/V) ---
        gemm_tc<true, true, false, false><<<dim3(2, 64, 1), 256, GEMM_SMEM_>>>(
            tgt, cW, cB, nullptr, qc, MROWS_, HID_, HID_, HID_, HID_, HID_, 0, 0, 0, 1.0f);
        { dim3 g(HEADS_, BN_); cross_u<<<g, 256>>>(cW + (size_t)HID_ * HID_); }
        // S = scale * U @ mem^T (batched over bn)
        gemm_tc<true, false, false, false><<<dim3(2, 1, BN_), 256, GEMM_SMEM_>>>(
            u, mem, nullptr, nullptr, s, 128, P2_, HID_, HID_, HID_, SPAD_,
            (long long)128 * HID_, (long long)P2_ * HID_, (long long)128 * SPAD_, scale);
        softmax_cross<<<(BN_ * 128) / 8, 256>>>();
        // T = A @ mem (batched, NT) — K=225; S pad cols are zero
        gemm_tc<false, false, false, false><<<dim3(2, 1, BN_), 256, GEMM_SMEM_>>>(
            s, mem, nullptr, nullptr, u, 128, HID_, P2_, SPAD_, HID_, HID_,
            (long long)128 * SPAD_, (long long)P2_ * HID_, (long long)128 * HID_, 1.0f);
        { dim3 g(HEADS_, BN_); cross_o<<<g, 512>>>(cW + (size_t)2 * HID_ * HID_, cB + 2 * HID_); }
        gemm_tc<true, true, true, false><<<dim3(2, 64, 1), 256, GEMM_SMEM_>>>(
            ctx, coW, coB, tgt, y, MROWS_, HID_, HID_, HID_, HID_, HID_, 0, 0, 0, 1.0f);
        layernorm_k<<<MROWS_ / 8, 256>>>(y, ln2_w + l * HID_, ln2_b + l * HID_, tgt);

        // --- FFN ---
        gemm_tc<true, true, false, true><<<dim3(8, 64, 1), 256, GEMM_SMEM_>>>(
            tgt, f1W, f1B, nullptr, ffn, MROWS_, FFN_, HID_, HID_, HID_, FFN_, 0, 0, 0, 1.0f);
        gemm_tc<true, true, true, false><<<dim3(2, 64, 1), 256, GEMM_SMEM_>>>(
            ffn, f2W, f2B, tgt, y, MROWS_, HID_, FFN_, FFN_, FFN_, HID_, 0, 0, 0, 1.0f);
        layernorm_k<<<MROWS_ / 8, 256>>>(y, ln3_w + l * HID_, ln3_b + l * HID_, tgt);
    }

    final_out<<<MROWS_ / 8, 256>>>(out_w, out_b, out);
}

// round 10
// speedup vs baseline: 1.3218x; 1.1561x over previous
#include <cuda_runtime.h>
#include <cuda_fp16.h>
#include <math.h>
#include <float.h>
#include <stdint.h>

#define B_      2
#define N_KP    256
#define C_      256
#define HF_     64
#define WF_     64
#define ROI_    15
#define P2_     225
#define HID_    256
#define HEADS_  8
#define DH_     32
#define DEPTH_  3
#define FFN_    1024
#define NQ_     16
#define BN_     512          // B_*N_KP
#define MROWS_  8192         // BN_*NQ_
#define MMEM_   115200       // BN_*P2_
#define SPAD_   240          // padded S row; cols 225..239 zeroed
#define LN_EPS_ 1e-5f

// fp16 GEMM smem: per stage per operand 5120 halves (A/TB: 128x40, NT: 32x136<=5120)
#define STG_HALVES_ 5120
#define GEMM_SMEM_  (3 * 2 * STG_HALVES_ * 2)    // 61440 B

// ---------------- scratch ----------------
__device__ float g_imgT[(size_t)B_ * HF_ * WF_ * C_];
__device__ float g_tgt [(size_t)MROWS_ * HID_];
__device__ float g_y   [(size_t)MROWS_ * HID_];
__device__ float g_qkv [(size_t)MROWS_ * 3 * HID_];
__device__ float g_qc  [(size_t)MROWS_ * HID_];
__device__ float g_u   [(size_t)BN_ * 128 * HID_];     // T (fp32)
__device__ float g_s   [(size_t)BN_ * 128 * SPAD_];
__device__ unsigned char g_valid[BN_];

// fp16 mirrors
__device__ __half g_feat_h[(size_t)MMEM_ * C_];
__device__ __half g_mem_h [(size_t)MMEM_ * C_];
__device__ __half g_tgt_h [(size_t)MROWS_ * HID_];
__device__ __half g_ctx_h [(size_t)MROWS_ * HID_];
__device__ __half g_uh    [(size_t)BN_ * 128 * HID_];  // U (fp16)
__device__ __half g_sh    [(size_t)BN_ * 128 * SPAD_];
__device__ __half g_ffn_h [(size_t)MROWS_ * FFN_];
// fp16 weights
__device__ __half g_projw_h[65536];
__device__ __half g_sqkv_h [3 * 3 * 65536];
__device__ __half g_sout_h [3 * 65536];
__device__ __half g_cqkv_h [3 * 3 * 65536];
__device__ __half g_cout_h [3 * 65536];
__device__ __half g_f1_h   [3 * 262144];
__device__ __half g_f2_h   [3 * 262144];

// ---------------- helpers ----------------
__device__ __forceinline__ void mma_f16(float* c, const uint32_t* a, const uint32_t* b) {
    asm volatile(
        "mma.sync.aligned.m16n8k16.row.col.f32.f16.f16.f32 "
        "{%0,%1,%2,%3}, {%4,%5,%6,%7}, {%8,%9}, {%0,%1,%2,%3};\n"
        : "+f"(c[0]), "+f"(c[1]), "+f"(c[2]), "+f"(c[3])
        : "r"(a[0]), "r"(a[1]), "r"(a[2]), "r"(a[3]), "r"(b[0]), "r"(b[1]));
}

__device__ __forceinline__ void ldsm4(uint32_t* r, uint32_t saddr) {
    asm volatile("ldmatrix.sync.aligned.m8n8.x4.shared.b16 {%0,%1,%2,%3}, [%4];\n"
                 : "=r"(r[0]), "=r"(r[1]), "=r"(r[2]), "=r"(r[3]) : "r"(saddr));
}
__device__ __forceinline__ void ldsm4t(uint32_t* r, uint32_t saddr) {
    asm volatile("ldmatrix.sync.aligned.m8n8.x4.trans.shared.b16 {%0,%1,%2,%3}, [%4];\n"
                 : "=r"(r[0]), "=r"(r[1]), "=r"(r[2]), "=r"(r[3]) : "r"(saddr));
}

__device__ __forceinline__ void cpa16(void* smem_ptr, const void* gptr, bool pred) {
    uint32_t sa = (uint32_t)__cvta_generic_to_shared(smem_ptr);
    int sz = pred ? 16 : 0;
    asm volatile("cp.async.cg.shared.global [%0], [%1], 16, %2;\n"
                 :: "r"(sa), "l"(gptr), "r"(sz));
}
#define CPA_COMMIT() asm volatile("cp.async.commit_group;\n")
#define CPA_WAIT(n)  asm volatile("cp.async.wait_group %0;\n" :: "n"(n))

// ---------------- small utility kernels ----------------
__global__ void f2h(const float* __restrict__ src, __half* __restrict__ dst, int n) {
    int i = blockIdx.x * 256 + threadIdx.x;
    if (i < n) dst[i] = __float2half_rn(src[i]);
}

__global__ void decode_mask(const unsigned char* __restrict__ m, unsigned char* __restrict__ out) {
    __shared__ int flag;
    if (threadIdx.x == 0) flag = 0;
    __syncthreads();
    int i = threadIdx.x;
    unsigned char v8 = m[i];
    if ((i & 3) != 0 && v8 != 0) atomicOr(&flag, 1);
    __syncthreads();
    if (flag) out[i] = (v8 != 0);
    else      out[i] = (((const int*)m)[i] != 0);
}

__global__ void transpose_img(const float* __restrict__ img) {
    int x = blockIdx.x, y = blockIdx.y, b = blockIdx.z, c = threadIdx.x;
    g_imgT[(((size_t)b * HF_ + y) * WF_ + x) * C_ + c] =
        img[(((size_t)b * C_ + c) * HF_ + y) * WF_ + x];
}

// ---------------- ROI bilinear gather -> fp16 feat ----------------
__global__ __launch_bounds__(256) void roi_gather(const float* __restrict__ kp) {
    int p = blockIdx.x, n = blockIdx.y, b = blockIdx.z, c = threadIdx.x;
    int iy = p / ROI_, ix = p % ROI_;
    float rc0 = rintf(kp[((size_t)b * N_KP + n) * 2 + 0]);
    float rc1 = rintf(kp[((size_t)b * N_KP + n) * 2 + 1]);
    float gy = rc0 + (float)(iy - 7);
    float gx = rc1 + (float)(ix - 7);
    float gxn = __fdiv_rn(gx, 511.0f) * 2.0f - 1.0f;
    float gyn = __fdiv_rn(gy, 511.0f) * 2.0f - 1.0f;
    bool invalid = (gxn < -1.0f) || (gyn < -1.0f) || (gxn > 1.0f) || (gyn > 1.0f);
    __half* dst = g_feat_h + ((size_t)((b * N_KP + n) * P2_ + p)) * C_;
    if (invalid) { dst[c] = __float2half_rn(0.0f); return; }
    float x = ((gxn + 1.0f) * (float)WF_ - 1.0f) * 0.5f;
    float y = ((gyn + 1.0f) * (float)HF_ - 1.0f) * 0.5f;
    float x0f = floorf(x), y0f = floorf(y);
    float wx = x - x0f, wy = y - y0f;
    int x0 = (int)x0f, y0 = (int)y0f;
    int x1 = x0 + 1, y1 = y0 + 1;
    float w00 = (1.0f - wy) * (1.0f - wx);
    float w01 = (1.0f - wy) * wx;
    float w10 = wy * (1.0f - wx);
    float w11 = wy * wx;
    float acc = 0.0f;
    if (y0 >= 0 && y0 < HF_) {
        const float* rowp = g_imgT + ((size_t)(b * HF_ + y0) * WF_) * C_;
        if (x0 >= 0 && x0 < WF_) acc += w00 * rowp[(size_t)x0 * C_ + c];
        if (x1 >= 0 && x1 < WF_) acc += w01 * rowp[(size_t)x1 * C_ + c];
    }
    if (y1 >= 0 && y1 < HF_) {
        const float* rowp = g_imgT + ((size_t)(b * HF_ + y1) * WF_) * C_;
        if (x0 >= 0 && x0 < WF_) acc += w10 * rowp[(size_t)x0 * C_ + c];
        if (x1 >= 0 && x1 < WF_) acc += w11 * rowp[(size_t)x1 * C_ + c];
    }
    dst[c] = __float2half_rn(acc);
}

// ================= fp16 GEMM (ldmatrix + 3-stage cp.async, K-tile 32) =================
// C = alpha * A @ op(B) [+ bias] [+ res] [relu]; A,B fp16; acc/bias/res fp32.
// TB=true : B is (N,K) row-major.  TB=false : B is (K,N) row-major.
// OUT16: C is __half*, else float*.
// Block 128x128, K-tile 32, 256 threads (8 warps 2Mx4N, warp tile 64x32).
template<bool TB, bool HAS_BIAS, bool HAS_RES, bool RELU, bool OUT16>
__global__ __launch_bounds__(256, 2) void gemm_h(
    const __half* __restrict__ A, const __half* __restrict__ B,
    const float* __restrict__ bias, const float* __restrict__ Res,
    void* __restrict__ Cv,
    int M, int N, int K, int lda, int ldb, int ldc,
    long long sA, long long sB, long long sC, float alpha)
{
    extern __shared__ __half hsm[];
    __half* Asm = hsm;                       // [3][128][40]
    __half* Bsm = hsm + 3 * STG_HALVES_;     // TB: [3][128][40]; NT: [3][32][136]

    long long z = blockIdx.z;
    A += z * sA; B += z * sB;
    float* Cf = (float*)Cv + (OUT16 ? 0 : z * sC);
    __half* Ch = (__half*)Cv + (OUT16 ? z * sC : 0);
    if (HAS_RES) Res += z * sC;

    int m0 = blockIdx.y * 128, n0 = blockIdx.x * 128;
    int t = threadIdx.x;
    int wid = t >> 5, lane = t & 31;
    int warp_m = wid >> 2;
    int warp_n = wid & 3;
    int g = lane >> 2, tq = lane & 3;
    (void)g; (void)tq;

    int l7 = lane & 7;
    int gidx = lane >> 3;

    uint32_t As_u = (uint32_t)__cvta_generic_to_shared(Asm);
    uint32_t Bs_u = (uint32_t)__cvta_generic_to_shared(Bsm);
    // byte offsets (halves *2)
    uint32_t a_lane  = (uint32_t)(((l7 + (gidx & 1) * 8) * 40 + (gidx >> 1) * 8) * 2);
    uint32_t bt_lane = a_lane;   // TB same geometry
    uint32_t bn_lane = (uint32_t)(((l7 + (gidx >> 1) * 8) * 136 + (gidx & 1) * 8) * 2);

    float acc[4][4][4];
#pragma unroll
    for (int i = 0; i < 4; i++)
#pragma unroll
        for (int j = 0; j < 4; j++)
#pragma unroll
            for (int r = 0; r < 4; r++) acc[i][j][r] = 0.0f;

    int KT = (K + 31) >> 5;

    auto load_tile = [&](int st, int k0) {
#pragma unroll
        for (int i = 0; i < 2; i++) {
            int lin = t + i * 256;
            int row = lin >> 2;
            int kc  = (lin & 3) * 8;
            int gm = m0 + row, gk = k0 + kc;
            cpa16(&Asm[st * STG_HALVES_ + row * 40 + kc],
                  A + (size_t)gm * lda + gk, gm < M && gk < K);
        }
        if (TB) {
#pragma unroll
            for (int i = 0; i < 2; i++) {
                int lin = t + i * 256;
                int row = lin >> 2;
                int kc  = (lin & 3) * 8;
                int gn = n0 + row, gk = k0 + kc;
                cpa16(&Bsm[st * STG_HALVES_ + row * 40 + kc],
                      B + (size_t)gn * ldb + gk, gn < N && gk < K);
            }
        } else {
#pragma unroll
            for (int i = 0; i < 2; i++) {
                int lin = t + i * 256;
                int kk = lin >> 4;
                int nc = (lin & 15) * 8;
                int gk = k0 + kk;
                cpa16(&Bsm[st * STG_HALVES_ + kk * 136 + nc],
                      B + (size_t)gk * ldb + n0 + nc, gk < K);
            }
        }
    };

    load_tile(0, 0); CPA_COMMIT();
    if (1 < KT) { load_tile(1, 32); CPA_COMMIT(); }

    for (int kt = 0; kt < KT; kt++) {
        if (kt + 1 < KT) { CPA_WAIT(1); } else { CPA_WAIT(0); }
        __syncthreads();
        if (kt + 2 < KT) { load_tile((kt + 2) % 3, (kt + 2) * 32); CPA_COMMIT(); }

        int st = kt % 3;
        uint32_t stoff = (uint32_t)(st * STG_HALVES_ * 2);
#pragma unroll
        for (int ks = 0; ks < 32; ks += 16) {
            uint32_t af[4][4];
#pragma unroll
            for (int mt = 0; mt < 4; mt++)
                ldsm4(af[mt], As_u + stoff +
                      (uint32_t)(((warp_m * 64 + mt * 16) * 40 + ks) * 2) + a_lane);
            uint32_t bf[4][2];
#pragma unroll
            for (int np = 0; np < 2; np++) {
                uint32_t tmp[4];
                if (TB) {
                    ldsm4(tmp, Bs_u + stoff +
                          (uint32_t)(((warp_n * 32 + np * 16) * 40 + ks) * 2) + bt_lane);
                } else {
                    ldsm4t(tmp, Bs_u + stoff +
                           (uint32_t)((ks * 136 + warp_n * 32 + np * 16) * 2) + bn_lane);
                }
                bf[2 * np][0]     = tmp[0]; bf[2 * np][1]     = tmp[2];
                bf[2 * np + 1][0] = tmp[1]; bf[2 * np + 1][1] = tmp[3];
            }
#pragma unroll
            for (int mt = 0; mt < 4; mt++)
#pragma unroll
                for (int nt = 0; nt < 4; nt++)
                    mma_f16(acc[mt][nt], af[mt], bf[nt]);
        }
    }

    // ---- epilogue ----
    int gq = lane >> 2, tq2 = lane & 3;
#pragma unroll
    for (int mt = 0; mt < 4; mt++) {
        int row0 = m0 + warp_m * 64 + mt * 16 + gq;
#pragma unroll
        for (int nt = 0; nt < 4; nt++) {
            int col = n0 + warp_n * 32 + nt * 8 + tq2 * 2;
#pragma unroll
            for (int half = 0; half < 2; half++) {
                int row = row0 + half * 8;
                if (row >= M) continue;
#pragma unroll
                for (int e = 0; e < 2; e++) {
                    int cc = col + e;
                    if (cc >= N) continue;
                    float v = acc[mt][nt][half * 2 + e] * alpha;
                    if (HAS_BIAS) v += bias[cc];
                    if (HAS_RES)  v += Res[(size_t)row * ldc + cc];
                    if (RELU)     v = fmaxf(v, 0.0f);
                    if (OUT16) Ch[(size_t)row * ldc + cc] = __float2half_rn(v);
                    else       Cf[(size_t)row * ldc + cc] = v;
                }
            }
        }
    }
}

// ---------------- tgt init ----------------
__global__ void init_tgt(const float* __restrict__ qe) {
    size_t i = (size_t)blockIdx.x * 256 + threadIdx.x;
    int c = (int)(i & 255);
    int q = (int)((i >> 8) & 15);
    float v = qe[q * HID_ + c];
    g_tgt[i] = v;
    g_tgt_h[i] = __float2half_rn(v);
}

// ---------------- self attention (fp32 in, fp16 ctx out) ----------------
__global__ __launch_bounds__(256) void self_attn() {
    int bn = blockIdx.x;
    __shared__ float sq[NQ_][260];
    __shared__ float sk[NQ_][260];
    __shared__ float sa[HEADS_][NQ_][NQ_ + 1];
    int t = threadIdx.x;
    const float* base = g_qkv + (size_t)bn * NQ_ * 768;
    for (int i = t; i < NQ_ * HID_; i += 256) {
        int q = i >> 8, c = i & 255;
        sq[q][c] = base[q * 768 + c];
        sk[q][c] = base[q * 768 + 256 + c];
    }
    __syncthreads();
    const float scale = 0.17677669529663687f;
    for (int i = t; i < HEADS_ * NQ_ * NQ_; i += 256) {
        int h = i >> 8, q = (i >> 4) & 15, kk = i & 15;
        float acc = 0.0f;
#pragma unroll
        for (int d = 0; d < DH_; d++) acc += sq[q][h * DH_ + d] * sk[kk][h * DH_ + d];
        sa[h][q][kk] = acc * scale;
    }
    __syncthreads();
    if (t < HEADS_ * NQ_) {
        int h = t >> 4, q = t & 15;
        float m = -FLT_MAX;
#pragma unroll
        for (int kk = 0; kk < NQ_; kk++) m = fmaxf(m, sa[h][q][kk]);
        float s = 0.0f;
#pragma unroll
        for (int kk = 0; kk < NQ_; kk++) { float e = expf(sa[h][q][kk] - m); sa[h][q][kk] = e; s += e; }
        float inv = 1.0f / s;
#pragma unroll
        for (int kk = 0; kk < NQ_; kk++) sa[h][q][kk] *= inv;
    }
    __syncthreads();
    __half* out = g_ctx_h + (size_t)bn * NQ_ * HID_;
    for (int i = t; i < NQ_ * HID_; i += 256) {
        int q = i >> 8, c = i & 255;
        int h = c >> 5;
        float acc = 0.0f;
#pragma unroll
        for (int kk = 0; kk < NQ_; kk++) acc += sa[h][q][kk] * base[kk * 768 + 512 + c];
        out[q * HID_ + c] = __float2half_rn(acc);
    }
}

// ---------------- cross-attn U = Q_h @ Wk_h (fp32 math, fp16 out) ----------------
__global__ __launch_bounds__(256) void cross_u(const float* __restrict__ Wk) {
    int h = blockIdx.x, bn = blockIdx.y;
    int c = threadIdx.x;
    __shared__ float sq[NQ_][DH_];
    for (int i = threadIdx.x; i < NQ_ * DH_; i += 256) {
        int q = i >> 5, d = i & 31;
        sq[q][d] = g_qc[((size_t)bn * NQ_ + q) * HID_ + h * DH_ + d];
    }
    __syncthreads();
    float acc[NQ_] = {};
#pragma unroll 4
    for (int d = 0; d < DH_; d++) {
        float w = Wk[(size_t)(h * DH_ + d) * HID_ + c];
#pragma unroll
        for (int q = 0; q < NQ_; q++) acc[q] += sq[q][d] * w;
    }
    __half* dst = g_uh + ((size_t)bn * 128 + h * NQ_) * HID_ + c;
#pragma unroll
    for (int q = 0; q < NQ_; q++) dst[(size_t)q * HID_] = __float2half_rn(acc[q]);
}

// ---------------- masked softmax (fp32 in g_s, fp16 out g_sh incl zero pad) ----------------
__global__ __launch_bounds__(256) void softmax_cross() {
    int row = blockIdx.x * 8 + (threadIdx.x >> 5);
    int lane = threadIdx.x & 31;
    int bn = row >> 7;
    bool v = g_valid[bn] != 0;
    const float* s = g_s + (size_t)row * SPAD_;
    __half* so = g_sh + (size_t)row * SPAD_;
    float vals[8];
    float m = -FLT_MAX;
#pragma unroll
    for (int i = 0; i < 8; i++) {
        int k = lane + i * 32;
        bool active = (k < P2_) && (v || k == 0);
        float x = active ? s[k] : -FLT_MAX;
        vals[i] = active ? x : -INFINITY;
        m = fmaxf(m, vals[i]);
    }
#pragma unroll
    for (int o = 16; o; o >>= 1) m = fmaxf(m, __shfl_xor_sync(0xffffffffu, m, o));
    float sum = 0.0f;
#pragma unroll
    for (int i = 0; i < 8; i++) {
        int k = lane + i * 32;
        bool active = (k < P2_) && (v || k == 0);
        float e = active ? expf(vals[i] - m) : 0.0f;
        vals[i] = e;
        sum += e;
    }
#pragma unroll
    for (int o = 16; o; o >>= 1) sum += __shfl_xor_sync(0xffffffffu, sum, o);
    float inv = 1.0f / sum;
#pragma unroll
    for (int i = 0; i < 8; i++) {
        int k = lane + i * 32;
        if (k < P2_)        so[k] = __float2half_rn(vals[i] * inv);
        else if (k < SPAD_) so[k] = __float2half_rn(0.0f);
    }
}

// ---------------- cross-attn output: ctx = T @ Wv_h^T + bv (fp16 ctx out) ----------------
__global__ __launch_bounds__(512) void cross_o(const float* __restrict__ Wv,
                                               const float* __restrict__ bv) {
    int h = blockIdx.x, bn = blockIdx.y;
    __shared__ float ws[DH_][HID_ + 1];
    int t = threadIdx.x;
    for (int i = t; i < DH_ * HID_; i += 512) {
        int d = i >> 8, c = i & 255;
        ws[d][c] = Wv[(size_t)(h * DH_ + d) * HID_ + c];
    }
    __syncthreads();
    int q = t >> 5, d = t & 31;
    const float* trow = g_u + ((size_t)bn * 128 + h * NQ_ + q) * HID_;
    float acc = 0.0f;
#pragma unroll 4
    for (int c = 0; c < HID_; c += 4) {
        float4 tv = *reinterpret_cast<const float4*>(trow + c);
        acc += tv.x * ws[d][c] + tv.y * ws[d][c + 1] + tv.z * ws[d][c + 2] + tv.w * ws[d][c + 3];
    }
    g_ctx_h[((size_t)bn * NQ_ + q) * HID_ + h * DH_ + d] = __float2half_rn(acc + bv[h * DH_ + d]);
}

// ---------------- layernorm: writes fp32 + fp16 ----------------
__global__ __launch_bounds__(256) void layernorm_k(const float* __restrict__ X,
                                                   const float* __restrict__ w,
                                                   const float* __restrict__ b,
                                                   float* __restrict__ Y,
                                                   __half* __restrict__ Y16) {
    int row = blockIdx.x * 8 + (threadIdx.x >> 5);
    int lane = threadIdx.x & 31;
    const float* x = X + (size_t)row * HID_;
    float v[8];
    float s = 0.0f;
#pragma unroll
    for (int i = 0; i < 8; i++) { v[i] = x[lane + i * 32]; s += v[i]; }
#pragma unroll
    for (int o = 16; o; o >>= 1) s += __shfl_xor_sync(0xffffffffu, s, o);
    float mu = s * (1.0f / 256.0f);
    float var = 0.0f;
#pragma unroll
    for (int i = 0; i < 8; i++) { float d = v[i] - mu; var += d * d; }
#pragma unroll
    for (int o = 16; o; o >>= 1) var += __shfl_xor_sync(0xffffffffu, var, o);
    var *= (1.0f / 256.0f);
    float r = rsqrtf(var + LN_EPS_);
    float* y = Y + (size_t)row * HID_;
    __half* y16 = Y16 + (size_t)row * HID_;
#pragma unroll
    for (int i = 0; i < 8; i++) {
        int c = lane + i * 32;
        float out = (v[i] - mu) * r * w[c] + b[c];
        y[c] = out;
        y16[c] = __float2half_rn(out);
    }
}

// ---------------- final head ----------------
__global__ __launch_bounds__(256) void final_out(const float* __restrict__ W,
                                                 const float* __restrict__ bias,
                                                 float* __restrict__ out) {
    int row = blockIdx.x * 8 + (threadIdx.x >> 5);
    int lane = threadIdx.x & 31;
    const float* x = g_tgt + (size_t)row * HID_;
    float acc[4] = {};
#pragma unroll
    for (int i = 0; i < 8; i++) {
        int c = lane + i * 32;
        float xv = x[c];
#pragma unroll
        for (int j = 0; j < 4; j++) acc[j] += xv * W[j * HID_ + c];
    }
#pragma unroll
    for (int j = 0; j < 4; j++)
#pragma unroll
        for (int o = 16; o; o >>= 1) acc[j] += __shfl_xor_sync(0xffffffffu, acc[j], o);
    if (lane < 4) out[(size_t)row * 4 + lane] = acc[lane] + bias[lane];
}

// ---------------- host ----------------
extern "C" void kernel_launch(void* const* d_in, const int* in_sizes, int n_in,
                              void* d_out, int out_size) {
    (void)in_sizes; (void)n_in; (void)out_size;
    const float* img         = (const float*)d_in[0];
    const float* kp          = (const float*)d_in[1];
    const unsigned char* msk = (const unsigned char*)d_in[2];
    const float* proj_w      = (const float*)d_in[3];
    const float* proj_b      = (const float*)d_in[4];
    const float* query_embed = (const float*)d_in[5];
    const float* self_qkv_w  = (const float*)d_in[6];
    const float* self_qkv_b  = (const float*)d_in[7];
    const float* self_out_w  = (const float*)d_in[8];
    const float* self_out_b  = (const float*)d_in[9];
    const float* cross_qkv_w = (const float*)d_in[10];
    const float* cross_qkv_b = (const float*)d_in[11];
    const float* cross_out_w = (const float*)d_in[12];
    const float* cross_out_b = (const float*)d_in[13];
    const float* ffn1_w      = (const float*)d_in[14];
    const float* ffn1_b      = (const float*)d_in[15];
    const float* ffn2_w      = (const float*)d_in[16];
    const float* ffn2_b      = (const float*)d_in[17];
    const float* ln1_w       = (const float*)d_in[18];
    const float* ln1_b       = (const float*)d_in[19];
    const float* ln2_w       = (const float*)d_in[20];
    const float* ln2_b       = (const float*)d_in[21];
    const float* ln3_w       = (const float*)d_in[22];
    const float* ln3_b       = (const float*)d_in[23];
    const float* out_w       = (const float*)d_in[24];
    const float* out_b       = (const float*)d_in[25];
    float* out = (float*)d_out;

    float *tgt, *y, *qkv, *qc, *u, *s;
    unsigned char* valid;
    __half *feat_h, *mem_h, *tgt_h, *ctx_h, *uh, *sh, *ffn_h;
    __half *projw_h, *sqkv_h, *sout_h, *cqkv_h, *cout_h, *f1_h, *f2_h;
    cudaGetSymbolAddress((void**)&tgt,   g_tgt);
    cudaGetSymbolAddress((void**)&y,     g_y);
    cudaGetSymbolAddress((void**)&qkv,   g_qkv);
    cudaGetSymbolAddress((void**)&qc,    g_qc);
    cudaGetSymbolAddress((void**)&u,     g_u);
    cudaGetSymbolAddress((void**)&s,     g_s);
    cudaGetSymbolAddress((void**)&valid, g_valid);
    cudaGetSymbolAddress((void**)&feat_h, g_feat_h);
    cudaGetSymbolAddress((void**)&mem_h,  g_mem_h);
    cudaGetSymbolAddress((void**)&tgt_h,  g_tgt_h);
    cudaGetSymbolAddress((void**)&ctx_h,  g_ctx_h);
    cudaGetSymbolAddress((void**)&uh,     g_uh);
    cudaGetSymbolAddress((void**)&sh,     g_sh);
    cudaGetSymbolAddress((void**)&ffn_h,  g_ffn_h);
    cudaGetSymbolAddress((void**)&projw_h, g_projw_h);
    cudaGetSymbolAddress((void**)&sqkv_h,  g_sqkv_h);
    cudaGetSymbolAddress((void**)&sout_h,  g_sout_h);
    cudaGetSymbolAddress((void**)&cqkv_h,  g_cqkv_h);
    cudaGetSymbolAddress((void**)&cout_h,  g_cout_h);
    cudaGetSymbolAddress((void**)&f1_h,    g_f1_h);
    cudaGetSymbolAddress((void**)&f2_h,    g_f2_h);

    cudaFuncSetAttribute((const void*)gemm_h<true,  true,  false, false, true>,
                         cudaFuncAttributeMaxDynamicSharedMemorySize, GEMM_SMEM_);
    cudaFuncSetAttribute((const void*)gemm_h<true,  true,  false, false, false>,
                         cudaFuncAttributeMaxDynamicSharedMemorySize, GEMM_SMEM_);
    cudaFuncSetAttribute((const void*)gemm_h<true,  true,  true,  false, false>,
                         cudaFuncAttributeMaxDynamicSharedMemorySize, GEMM_SMEM_);
    cudaFuncSetAttribute((const void*)gemm_h<true,  false, false, false, false>,
                         cudaFuncAttributeMaxDynamicSharedMemorySize, GEMM_SMEM_);
    cudaFuncSetAttribute((const void*)gemm_h<false, false, false, false, false>,
                         cudaFuncAttributeMaxDynamicSharedMemorySize, GEMM_SMEM_);
    cudaFuncSetAttribute((const void*)gemm_h<true,  true,  false, true,  true>,
                         cudaFuncAttributeMaxDynamicSharedMemorySize, GEMM_SMEM_);

    const float scale = 0.17677669529663687f;

    decode_mask<<<1, 512>>>(msk, valid);
    { dim3 g(WF_, HF_, B_); transpose_img<<<g, C_>>>(img); }
    { dim3 g(P2_, N_KP, B_); roi_gather<<<g, C_>>>(kp); }

    // weight converts (once; deterministic each call)
    f2h<<<(65536 + 255) / 256, 256>>>(proj_w, projw_h, 65536);
    f2h<<<(589824 + 255) / 256, 256>>>(self_qkv_w, sqkv_h, 589824);
    f2h<<<(196608 + 255) / 256, 256>>>(self_out_w, sout_h, 196608);
    f2h<<<(589824 + 255) / 256, 256>>>(cross_qkv_w, cqkv_h, 589824);
    f2h<<<(196608 + 255) / 256, 256>>>(cross_out_w, cout_h, 196608);
    f2h<<<(786432 + 255) / 256, 256>>>(ffn1_w, f1_h, 786432);
    f2h<<<(786432 + 255) / 256, 256>>>(ffn2_w, f2_h, 786432);

    // mem_h = fp16(feat @ proj_w^T + proj_b)
    gemm_h<true, true, false, false, true><<<dim3(2, 900, 1), 256, GEMM_SMEM_>>>(
        feat_h, projw_h, proj_b, nullptr, mem_h, MMEM_, HID_, C_, C_, C_, HID_, 0, 0, 0, 1.0f);

    init_tgt<<<MROWS_, 256>>>(query_embed);

    for (int l = 0; l < DEPTH_; l++) {
        const __half* sW  = sqkv_h + (size_t)l * 3 * 65536;
        const float*  sB  = self_qkv_b  + (size_t)l * 3 * HID_;
        const __half* soW = sout_h + (size_t)l * 65536;
        const float*  soB = self_out_b  + (size_t)l * HID_;
        const __half* cWq = cqkv_h + (size_t)l * 3 * 65536;
        const float*  cB  = cross_qkv_b + (size_t)l * 3 * HID_;
        const float*  cWf = cross_qkv_w + (size_t)l * 3 * HID_ * HID_;  // fp32 for cross_u/cross_o
        const __half* coW = cout_h + (size_t)l * 65536;
        const float*  coB = cross_out_b + (size_t)l * HID_;
        const __half* f1W = f1_h + (size_t)l * 262144;
        const float*  f1B = ffn1_b + (size_t)l * FFN_;
        const __half* f2W = f2_h + (size_t)l * 262144;
        const float*  f2B = ffn2_b + (size_t)l * HID_;

        // --- self attention ---
        gemm_h<true, true, false, false, false><<<dim3(6, 64, 1), 256, GEMM_SMEM_>>>(
            tgt_h, sW, sB, nullptr, qkv, MROWS_, 3 * HID_, HID_, HID_, HID_, 3 * HID_, 0, 0, 0, 1.0f);
        self_attn<<<BN_, 256>>>();
        gemm_h<true, true, true, false, false><<<dim3(2, 64, 1), 256, GEMM_SMEM_>>>(
            ctx_h, soW, soB, tgt, y, MROWS_, HID_, HID_, HID_, HID_, HID_, 0, 0, 0, 1.0f);
        layernorm_k<<<MROWS_ / 8, 256>>>(y, ln1_w + l * HID_, ln1_b + l * HID_, tgt, tgt_h);

        // --- cross attention (factored K/V) ---
        gemm_h<true, true, false, false, false><<<dim3(2, 64, 1), 256, GEMM_SMEM_>>>(
            tgt_h, cWq, cB, nullptr, qc, MROWS_, HID_, HID_, HID_, HID_, HID_, 0, 0, 0, 1.0f);
        { dim3 g(HEADS_, BN_); cross_u<<<g, 256>>>(cWf + (size_t)HID_ * HID_); }
        // S = scale * U @ mem^T (batched over bn)
        gemm_h<true, false, false, false, false><<<dim3(2, 1, BN_), 256, GEMM_SMEM_>>>(
            uh, mem_h, nullptr, nullptr, s, 128, P2_, HID_, HID_, HID_, SPAD_,
            (long long)128 * HID_, (long long)P2_ * HID_, (long long)128 * SPAD_, scale);
        softmax_cross<<<(BN_ * 128) / 8, 256>>>();
        // T = A @ mem (batched, NT) — K=225; s_h pad cols are zero
        gemm_h<false, false, false, false, false><<<dim3(2, 1, BN_), 256, GEMM_SMEM_>>>(
            sh, mem_h, nullptr, nullptr, u, 128, HID_, P2_, SPAD_, HID_, HID_,
            (long long)128 * SPAD_, (long long)P2_ * HID_, (long long)128 * HID_, 1.0f);
        { dim3 g(HEADS_, BN_); cross_o<<<g, 512>>>(cWf + (size_t)2 * HID_ * HID_, cB + 2 * HID_); }
        gemm_h<true, true, true, false, false><<<dim3(2, 64, 1), 256, GEMM_SMEM_>>>(
            ctx_h, coW, coB, tgt, y, MROWS_, HID_, HID_, HID_, HID_, HID_, 0, 0, 0, 1.0f);
        layernorm_k<<<MROWS_ / 8, 256>>>(y, ln2_w + l * HID_, ln2_b + l * HID_, tgt, tgt_h);

        // --- FFN ---
        gemm_h<true, true, false, true, true><<<dim3(8, 64, 1), 256, GEMM_SMEM_>>>(
            tgt_h, f1W, f1B, nullptr, ffn_h, MROWS_, FFN_, HID_, HID_, HID_, FFN_, 0, 0, 0, 1.0f);
        gemm_h<true, true, true, false, false><<<dim3(2, 64, 1), 256, GEMM_SMEM_>>>(
            ffn_h, f2W, f2B, tgt, y, MROWS_, HID_, FFN_, FFN_, FFN_, HID_, 0, 0, 0, 1.0f);
        layernorm_k<<<MROWS_ / 8, 256>>>(y, ln3_w + l * HID_, ln3_b + l * HID_, tgt, tgt_h);
    }

    final_out<<<MROWS_ / 8, 256>>>(out_w, out_b, out);
}